// round 9
// baseline (speedup 1.0000x reference)
#include <cuda_runtime.h>
#include <cstdint>

// ============================================================================
// ProteinSpatioTemporalAttention — round 8 (resubmit; prior run died to the
// same container-infra failure seen in round 6, which benched fine on retry):
//  round-7 structure (fused expand+RoPE attention, Beff gate, merged QKV)
//  + permuted-K fragment mapping: slot pair (t,t+4) -> columns (2t,2t+1) in
//    BOTH mma operands, making every fragment load a vectorized LDS.64 and
//    eliminating all PV shuffles in attention (score c-frag == P a-frag).
//    GEMM PAD 36->40, attn qs/ks stride 68->72, vs 24->20 (bank-verified).
// ============================================================================

namespace {
constexpr int B_  = 4;
constexpr int T_  = 64;
constexpr int L_  = 256;
constexpr int C_  = 512;
constexpr int RK_ = 128;
constexpr int N_  = B_ * T_ * L_;   // 65536 tokens

constexpr int PAD_ = 40;            // GEMM smem row stride (floats), LDS.64-safe
constexpr int GEMM_SMEM = 2 * 2 * 128 * PAD_ * 4;   // 81920 bytes

// attention dynamic smem layout (floats)
constexpr int QKP_ = 72;                  // qs/ks row stride (LDS.64-safe)
constexpr int VP_  = 20;                  // vs row stride
constexpr int AT_QS  = 0;                 // 64*72
constexpr int AT_KS  = AT_QS + 64 * QKP_; // 64*72
constexpr int AT_VS  = AT_KS + 64 * QKP_; // 64*20
constexpr int AT_UT  = AT_VS + 64 * VP_;  // 16*66
constexpr int AT_LOT = AT_UT + 16 * 66;   // 16*65
constexpr int AT_TOT = AT_LOT + 16 * 65;
constexpr int ATTN_SMEM = AT_TOT * 4;     // 50368 bytes
}

// -------------------- scratch (device globals; no cudaMalloc) ---------------
__device__ float g_xn [N_ * C_];
__device__ float g_y  [N_ * C_];
__device__ float g_x1 [N_ * C_];
__device__ float g_x2 [N_ * C_];
__device__ float g_qlo[N_ * RK_];
__device__ float g_klo[N_ * RK_];
__device__ float g_vlo[N_ * RK_];
__device__ float g_olo[N_ * RK_];
__device__ float g_befft[512 * 640];
__device__ float g_beffa[512 * 640];
__device__ float g_ropec[256 * 32];
__device__ float g_ropes[256 * 32];

// ============================ PTX helpers ===================================
__device__ __forceinline__ uint32_t smem_u32(const void* p) {
    uint32_t a;
    asm("{ .reg .u64 t; cvta.to.shared.u64 t, %1; cvt.u32.u64 %0, t; }"
        : "=r"(a) : "l"(p));
    return a;
}
__device__ __forceinline__ uint32_t f2tf(float x) {
    uint32_t r;
    asm("cvt.rna.tf32.f32 %0, %1;" : "=r"(r) : "f"(x));
    return r;
}
__device__ __forceinline__ void mma_tf32(float* c, const uint32_t* a, const uint32_t* b) {
    asm volatile("mma.sync.aligned.m16n8k8.row.col.f32.tf32.tf32.f32 "
        "{%0,%1,%2,%3}, {%4,%5,%6,%7}, {%8,%9}, {%0,%1,%2,%3};"
        : "+f"(c[0]), "+f"(c[1]), "+f"(c[2]), "+f"(c[3])
        : "r"(a[0]), "r"(a[1]), "r"(a[2]), "r"(a[3]), "r"(b[0]), "r"(b[1]));
}
#define CP_ASYNC16(dst, src) \
    asm volatile("cp.async.cg.shared.global [%0], [%1], 16;" :: "r"(dst), "l"(src))
#define CP_COMMIT() asm volatile("cp.async.commit_group;" ::: "memory")
#define CP_WAIT1()  asm volatile("cp.async.wait_group 1;" ::: "memory")
#define CP_WAIT0()  asm volatile("cp.async.wait_group 0;" ::: "memory")

// ============================ tf32 mma GEMM body ============================
// Permuted-K fragments: thread slot pair (t, t+4) holds k-columns (2t, 2t+1)
// for BOTH A and B -> LDS.64 fragment loads; result identical.
__device__ __forceinline__
void gemm_body(const float* __restrict__ A0, int lda0,
               const float* __restrict__ A1, int lda1,
               const float* __restrict__ Bw,
               const float* __restrict__ bias,
               const float* __restrict__ resid,
               const float* __restrict__ yv,
               float* __restrict__ C, int ldc,
               int K1, int Kw, int mode, int m0, int n0)
{
    extern __shared__ float sm[];
    float* As = sm;
    float* Bs = sm + 2 * 128 * PAD_;

    const int tid  = threadIdx.x;
    const int lane = tid & 31;
    const int wid  = tid >> 5;
    const int NC   = Kw >> 5;
    const int NC1  = K1 >> 5;

    const int lr = tid >> 3;
    const int lk = (tid & 7) * 4;

    const uint32_t aS0 = smem_u32(As);
    const uint32_t bS0 = smem_u32(Bs);

    auto prefetch = [&](int c, int s) {
        const float* Ap; int kb, lda;
        if (c < NC1) { Ap = A0; lda = lda0; kb = c * 32; }
        else         { Ap = A1; lda = lda1; kb = (c - NC1) * 32; }
        const uint32_t aT = aS0 + (uint32_t)(s * 128 * PAD_) * 4;
        const uint32_t bT = bS0 + (uint32_t)(s * 128 * PAD_) * 4;
        const float* srcB = Bw + (size_t)n0 * Kw + c * 32;
        #pragma unroll
        for (int it = 0; it < 4; ++it) {
            const int r = lr + it * 32;
            CP_ASYNC16(aT + (uint32_t)(r * PAD_ + lk) * 4,
                       Ap + (size_t)(m0 + r) * lda + kb + lk);
            CP_ASYNC16(bT + (uint32_t)(r * PAD_ + lk) * 4,
                       srcB + (size_t)r * Kw + lk);
        }
    };

    const int wm = (wid & 1) * 64;
    const int wn = (wid >> 1) * 32;
    const int qr = lane >> 2;
    const int tc = lane & 3;

    float acc[4][4][4];
    #pragma unroll
    for (int i = 0; i < 4; ++i)
        #pragma unroll
        for (int j = 0; j < 4; ++j)
            #pragma unroll
            for (int r = 0; r < 4; ++r) acc[i][j][r] = 0.f;

    prefetch(0, 0);
    CP_COMMIT();

    for (int c = 0; c < NC; ++c) {
        const int s = c & 1;
        if (c + 1 < NC) { prefetch(c + 1, s ^ 1); CP_COMMIT(); CP_WAIT1(); }
        else            { CP_WAIT0(); }
        __syncthreads();

        // fragment bases: row-major [row][k], thread k-columns 2tc, 2tc+1
        const float* a_s = As + s * 128 * PAD_ + (wm + qr) * PAD_ + 2 * tc;
        const float* b_s = Bs + s * 128 * PAD_ + (wn + qr) * PAD_ + 2 * tc;

        #pragma unroll
        for (int ks = 0; ks < 4; ++ks) {
            const int k0 = ks * 8;
            uint32_t af[4][4];
            #pragma unroll
            for (int i = 0; i < 4; ++i) {
                float2 a0 = *(const float2*)(a_s + i * 16 * PAD_ + k0);
                float2 a1 = *(const float2*)(a_s + i * 16 * PAD_ + 8 * PAD_ + k0);
                af[i][0] = f2tf(a0.x);   // A[g][2t]
                af[i][1] = f2tf(a1.x);   // A[g+8][2t]
                af[i][2] = f2tf(a0.y);   // A[g][2t+1]
                af[i][3] = f2tf(a1.y);   // A[g+8][2t+1]
            }
            #pragma unroll
            for (int j = 0; j < 4; ++j) {
                float2 bb = *(const float2*)(b_s + j * 8 * PAD_ + k0);
                uint32_t bf[2] = { f2tf(bb.x), f2tf(bb.y) };
                #pragma unroll
                for (int i = 0; i < 4; ++i) mma_tf32(acc[i][j], af[i], bf);
            }
        }
        __syncthreads();
    }

    const int row0 = m0 + wm + qr;
    const int col0 = n0 + wn + tc * 2;

    #pragma unroll
    for (int i = 0; i < 4; ++i) {
        #pragma unroll
        for (int half = 0; half < 2; ++half) {
            const int r = row0 + i * 16 + half * 8;
            float*       crow = C + (size_t)r * ldc;
            const float* rrow = resid ? resid + (size_t)r * ldc : nullptr;
            const float* yrow = yv    ? yv    + (size_t)r * ldc : nullptr;
            #pragma unroll
            for (int j = 0; j < 4; ++j) {
                const int cc = col0 + j * 8;
                float v0 = acc[i][j][half * 2 + 0];
                float v1 = acc[i][j][half * 2 + 1];
                if (mode == 0) {
                    *(float2*)(crow + cc) = make_float2(v0, v1);
                } else if (mode == 1) {
                    float2 bi = *(const float2*)(bias + cc);
                    float2 rv = *(const float2*)(rrow + cc);
                    float2 yw = *(const float2*)(yrow + cc);
                    float g0 = 1.f / (1.f + __expf(-(v0 + bi.x)));
                    float g1 = 1.f / (1.f + __expf(-(v1 + bi.y)));
                    *(float2*)(crow + cc) = make_float2(
                        g0 * rv.x + (1.f - g0) * yw.x,
                        g1 * rv.y + (1.f - g1) * yw.y);
                } else {
                    float2 bi = *(const float2*)(bias + cc);
                    float2 rv = *(const float2*)(rrow + cc);
                    *(float2*)(crow + cc) = make_float2(v0 + bi.x + rv.x,
                                                        v1 + bi.y + rv.y);
                }
            }
        }
    }
}

__global__ __launch_bounds__(256, 2)
void gemm_qkv(const float* __restrict__ A,
              const float* __restrict__ Wq, const float* __restrict__ Wk,
              const float* __restrict__ Wv,
              float* __restrict__ q, float* __restrict__ k, float* __restrict__ v)
{
    const int bx  = blockIdx.x;
    const int sel = bx % 3;
    const int m0  = (bx / 3) * 128;
    const float* Bw = (sel == 0) ? Wq : (sel == 1) ? Wk : Wv;
    float*       C  = (sel == 0) ? q  : (sel == 1) ? k  : v;
    gemm_body(A, 512, A, 512, Bw, nullptr, nullptr, nullptr, C, 128,
              512, 512, 0, m0, 0);
}

__global__ __launch_bounds__(256, 2)
void gemm_gen(const float* __restrict__ A0, int lda0,
              const float* __restrict__ A1, int lda1,
              const float* __restrict__ Bw,
              const float* __restrict__ bias,
              const float* __restrict__ resid,
              const float* __restrict__ yv,
              float* __restrict__ C, int K1, int Kw, int mode)
{
    const int bx = blockIdx.x;
    const int m0 = (bx >> 2) * 128;
    const int n0 = (bx & 3) * 128;
    gemm_body(A0, lda0, A1, lda1, Bw, bias, resid, yv, C, 512,
              K1, Kw, mode, m0, n0);
}

// ============================ prep kernels ==================================
__global__ void build_beff(const float* __restrict__ gW,
                           const float* __restrict__ V,
                           float* __restrict__ Beff)
{
    const int n = blockIdx.x;
    const int tid = threadIdx.x;
    ((float4*)(Beff + (size_t)n * 640))[tid] =
        ((const float4*)(gW + (size_t)n * 1024))[tid];
    const int h = tid >> 4, r = tid & 15;
    const float* w2 = gW + (size_t)n * 1024 + 512 + h * 64;
    const float* vr = V + (size_t)(h * 16 + r) * 64;
    float s = 0.f;
    #pragma unroll
    for (int d = 0; d < 64; ++d) s = fmaf(w2[d], vr[d], s);
    Beff[(size_t)n * 640 + 512 + tid] = s;
}

__global__ void build_rope(float* __restrict__ rc, float* __restrict__ rs)
{
    const int idx = blockIdx.x * 256 + threadIdx.x;
    const int pos = idx >> 5;
    const int ih  = idx & 31;
    const float theta = expf((float)ih * -0.28782313662425572f);
    float sn, cs;
    sincosf((float)pos * theta, &sn, &cs);
    rc[idx] = cs;  rs[idx] = sn;
}

// ============================ LayerNorm =====================================
__global__ void ln_kernel(const float* __restrict__ x,
                          const float* __restrict__ g,
                          const float* __restrict__ b,
                          float* __restrict__ out)
{
    const int n   = blockIdx.x;
    const int tid = threadIdx.x;
    const float* xr = x + (size_t)n * C_;

    float v0 = xr[tid];
    float v1 = xr[tid + 256];
    float s = v0 + v1;
    float q = v0 * v0 + v1 * v1;
    #pragma unroll
    for (int o = 16; o; o >>= 1) {
        s += __shfl_xor_sync(0xffffffffu, s, o);
        q += __shfl_xor_sync(0xffffffffu, q, o);
    }
    __shared__ float rs[8], rq[8];
    if ((tid & 31) == 0) { rs[tid >> 5] = s; rq[tid >> 5] = q; }
    __syncthreads();
    float st = 0.f, qt = 0.f;
    #pragma unroll
    for (int w = 0; w < 8; ++w) { st += rs[w]; qt += rq[w]; }

    const float mean = st * (1.f / 512.f);
    const float var  = qt * (1.f / 512.f) - mean * mean;
    const float rstd = rsqrtf(var + 1e-12f);

    float* orow = out + (size_t)n * C_;
    orow[tid]       = (v0 - mean) * rstd * g[tid]       + b[tid];
    orow[tid + 256] = (v1 - mean) * rstd * g[tid + 256] + b[tid + 256];
}

// ===================== fused mma flash attention ============================
// 128 threads (4 warps). Block = (sequence, head, 64-row q-tile).
// Expands q/k from rank space (U[h]) + RoPE inside the kernel.
// Permuted-K fragments: LDS.64 score loads; shuffle-free PV (score c-frag
// layout coincides with P a-frag under the same permutation).
template <int KV_TILES, bool TIME>
__global__ __launch_bounds__(128)
void attn_fused(const float* __restrict__ qlo, const float* __restrict__ klo,
                const float* __restrict__ vlow, const float* __restrict__ U,
                const float* __restrict__ rc, const float* __restrict__ rs,
                float* __restrict__ olow)
{
    extern __shared__ float sm[];
    float* qs  = sm + AT_QS;    // [64][72]
    float* ks  = sm + AT_KS;    // [64][72]
    float* vs  = sm + AT_VS;    // [64][20]
    float* Ut  = sm + AT_UT;    // [16][66]
    float* lot = sm + AT_LOT;   // [16][65]

    const int tid  = threadIdx.x;
    const int lane = tid & 31;
    const int w    = tid >> 5;
    const int head = blockIdx.y;

    int base, step;
    if (TIME) {
        const int b = blockIdx.x >> 8;
        const int l = blockIdx.x & 255;
        base = b * (T_ * L_) + l;  step = L_;
    } else {
        base = blockIdx.x * L_;    step = 1;
    }
    const int q0 = blockIdx.z * 64;

    const int ei    = tid >> 1;
    const int ehalf = tid & 1;

    // ---- load U[h] transposed ----
    #pragma unroll
    for (int p = 0; p < 2; ++p) {
        const int idx = tid + p * 128;
        const int d = idx >> 2, r4 = (idx & 3) * 4;
        float4 u = *(const float4*)(U + ((size_t)head * 64 + d) * 16 + r4);
        Ut[(r4 + 0) * 66 + d] = u.x;
        Ut[(r4 + 1) * 66 + d] = u.y;
        Ut[(r4 + 2) * 66 + d] = u.z;
        Ut[(r4 + 3) * 66 + d] = u.w;
    }
    // ---- load qlo tile transposed ----
    #pragma unroll
    for (int p = 0; p < 2; ++p) {
        const int idx = tid + p * 128;
        const int i = idx >> 2, r4 = (idx & 3) * 4;
        const int tok = base + (q0 + i) * step;
        float4 v = *(const float4*)(qlo + (size_t)tok * RK_ + head * 16 + r4);
        lot[(r4 + 0) * 65 + i] = v.x;
        lot[(r4 + 1) * 65 + i] = v.y;
        lot[(r4 + 2) * 65 + i] = v.z;
        lot[(r4 + 3) * 65 + i] = v.w;
    }
    __syncthreads();

    // ---- expand Q + RoPE + scale ----
    {
        float qe[16], qo[16];
        #pragma unroll
        for (int pp = 0; pp < 16; ++pp) { qe[pp] = 0.f; qo[pp] = 0.f; }
        #pragma unroll
        for (int r = 0; r < 16; ++r) {
            const float lv = lot[r * 65 + ei];
            const float* ur = Ut + r * 66 + ehalf * 32;
            #pragma unroll
            for (int pp = 0; pp < 16; ++pp) {
                qe[pp] = fmaf(ur[2 * pp],     lv, qe[pp]);
                qo[pp] = fmaf(ur[2 * pp + 1], lv, qo[pp]);
            }
        }
        const int pos = q0 + ei;
        #pragma unroll
        for (int pp = 0; pp < 16; ++pp) {
            const int ih = ehalf * 16 + pp;
            const float cs = __ldg(rc + pos * 32 + ih);
            const float sn = __ldg(rs + pos * 32 + ih);
            qs[ei * QKP_ + 2 * ih]     = (qe[pp] * cs - qo[pp] * sn) * 0.125f;
            qs[ei * QKP_ + 2 * ih + 1] = (qe[pp] * sn + qo[pp] * cs) * 0.125f;
        }
    }
    __syncthreads();

    const int qr = lane >> 2;
    const int c  = lane & 3;

    float m0v = -1e30f, m1v = -1e30f, l0v = 0.f, l1v = 0.f;
    float accO[2][4];
    #pragma unroll
    for (int nf = 0; nf < 2; ++nf)
        #pragma unroll
        for (int r = 0; r < 4; ++r) accO[nf][r] = 0.f;

    for (int kt = 0; kt < KV_TILES; ++kt) {
        // ---- load klo tile (transposed) + V tile ----
        #pragma unroll
        for (int p = 0; p < 2; ++p) {
            const int idx = tid + p * 128;
            const int i = idx >> 2, r4 = (idx & 3) * 4;
            const int tok = base + (kt * 64 + i) * step;
            float4 v = *(const float4*)(klo + (size_t)tok * RK_ + head * 16 + r4);
            lot[(r4 + 0) * 65 + i] = v.x;
            lot[(r4 + 1) * 65 + i] = v.y;
            lot[(r4 + 2) * 65 + i] = v.z;
            lot[(r4 + 3) * 65 + i] = v.w;
        }
        #pragma unroll
        for (int p = 0; p < 2; ++p) {
            const int f = tid + p * 128;
            const int j = f >> 2;
            const int rq = (f & 3) * 4;
            const int tok = base + (kt * 64 + j) * step;
            *(float4*)&vs[j * VP_ + rq] =
                *(const float4*)(vlow + (size_t)tok * RK_ + head * 16 + rq);
        }
        __syncthreads();

        // ---- expand K + RoPE ----
        {
            float ke[16], ko[16];
            #pragma unroll
            for (int pp = 0; pp < 16; ++pp) { ke[pp] = 0.f; ko[pp] = 0.f; }
            #pragma unroll
            for (int r = 0; r < 16; ++r) {
                const float lv = lot[r * 65 + ei];
                const float* ur = Ut + r * 66 + ehalf * 32;
                #pragma unroll
                for (int pp = 0; pp < 16; ++pp) {
                    ke[pp] = fmaf(ur[2 * pp],     lv, ke[pp]);
                    ko[pp] = fmaf(ur[2 * pp + 1], lv, ko[pp]);
                }
            }
            const int pos = kt * 64 + ei;
            #pragma unroll
            for (int pp = 0; pp < 16; ++pp) {
                const int ih = ehalf * 16 + pp;
                const float cs = __ldg(rc + pos * 32 + ih);
                const float sn = __ldg(rs + pos * 32 + ih);
                ks[ei * QKP_ + 2 * ih]     = ke[pp] * cs - ko[pp] * sn;
                ks[ei * QKP_ + 2 * ih + 1] = ke[pp] * sn + ko[pp] * cs;
            }
        }
        __syncthreads();

        // ---- scores S[16 x 64] per warp via mma (LDS.64 fragments) ----
        float s[8][4];
        #pragma unroll
        for (int j = 0; j < 8; ++j)
            #pragma unroll
            for (int r = 0; r < 4; ++r) s[j][r] = 0.f;

        const float* a_s = qs + (w * 16 + qr) * QKP_ + 2 * c;
        const float* b_s = ks + qr * QKP_ + 2 * c;
        #pragma unroll
        for (int ks8 = 0; ks8 < 8; ++ks8) {
            const int k0 = ks8 * 8;
            float2 a0 = *(const float2*)(a_s + k0);
            float2 a1 = *(const float2*)(a_s + 8 * QKP_ + k0);
            uint32_t af[4];
            af[0] = f2tf(a0.x);
            af[1] = f2tf(a1.x);
            af[2] = f2tf(a0.y);
            af[3] = f2tf(a1.y);
            #pragma unroll
            for (int j = 0; j < 8; ++j) {
                float2 bb = *(const float2*)(b_s + j * 8 * QKP_ + k0);
                uint32_t bf[2] = { f2tf(bb.x), f2tf(bb.y) };
                mma_tf32(s[j], af, bf);
            }
        }

        // ---- online softmax (registers + quad shuffles) ----
        float tm0 = -1e30f, tm1 = -1e30f;
        #pragma unroll
        for (int j = 0; j < 8; ++j) {
            tm0 = fmaxf(tm0, fmaxf(s[j][0], s[j][1]));
            tm1 = fmaxf(tm1, fmaxf(s[j][2], s[j][3]));
        }
        tm0 = fmaxf(tm0, __shfl_xor_sync(0xffffffffu, tm0, 1));
        tm0 = fmaxf(tm0, __shfl_xor_sync(0xffffffffu, tm0, 2));
        tm1 = fmaxf(tm1, __shfl_xor_sync(0xffffffffu, tm1, 1));
        tm1 = fmaxf(tm1, __shfl_xor_sync(0xffffffffu, tm1, 2));

        const float mn0 = fmaxf(m0v, tm0);
        const float mn1 = fmaxf(m1v, tm1);
        const float al0 = __expf(m0v - mn0);
        const float al1 = __expf(m1v - mn1);
        m0v = mn0; m1v = mn1;

        float rs0 = 0.f, rs1 = 0.f;
        #pragma unroll
        for (int j = 0; j < 8; ++j) {
            s[j][0] = __expf(s[j][0] - mn0);
            s[j][1] = __expf(s[j][1] - mn0);
            s[j][2] = __expf(s[j][2] - mn1);
            s[j][3] = __expf(s[j][3] - mn1);
            rs0 += s[j][0] + s[j][1];
            rs1 += s[j][2] + s[j][3];
        }
        rs0 += __shfl_xor_sync(0xffffffffu, rs0, 1);
        rs0 += __shfl_xor_sync(0xffffffffu, rs0, 2);
        rs1 += __shfl_xor_sync(0xffffffffu, rs1, 1);
        rs1 += __shfl_xor_sync(0xffffffffu, rs1, 2);
        l0v = l0v * al0 + rs0;
        l1v = l1v * al1 + rs1;

        #pragma unroll
        for (int nf = 0; nf < 2; ++nf) {
            accO[nf][0] *= al0; accO[nf][1] *= al0;
            accO[nf][2] *= al1; accO[nf][3] *= al1;
        }

        // ---- PV: score c-frag IS the P a-frag under permuted-K mapping ----
        // a-frag slots: a0=P[g][2c], a1=P[g+8][2c], a2=P[g][2c+1], a3=P[g+8][2c+1]
        //             =  s[j][0],     s[j][2],       s[j][1],       s[j][3]
        // V b-frag: slot t -> key j*8+2c (row), slot t+4 -> key j*8+2c+1.
        #pragma unroll
        for (int j = 0; j < 8; ++j) {
            uint32_t pa[4];
            pa[0] = f2tf(s[j][0]);
            pa[1] = f2tf(s[j][2]);
            pa[2] = f2tf(s[j][1]);
            pa[3] = f2tf(s[j][3]);
            const float* vp = vs + (j * 8 + 2 * c) * VP_;
            #pragma unroll
            for (int nf = 0; nf < 2; ++nf) {
                const int col = nf * 8 + qr;
                uint32_t bf[2] = { f2tf(vp[col]), f2tf(vp[VP_ + col]) };
                mma_tf32(accO[nf], pa, bf);
            }
        }
        __syncthreads();
    }

    // ---- epilogue ----
    const float inv0 = 1.f / l0v;
    const float inv1 = 1.f / l1v;
    const int r0 = q0 + w * 16 + qr;
    const int r1 = r0 + 8;
    const size_t tok0 = (size_t)(base + r0 * step) * RK_ + head * 16;
    const size_t tok1 = (size_t)(base + r1 * step) * RK_ + head * 16;
    #pragma unroll
    for (int nf = 0; nf < 2; ++nf) {
        const int col = nf * 8 + c * 2;
        *(float2*)(olow + tok0 + col) = make_float2(accO[nf][0] * inv0,
                                                    accO[nf][1] * inv0);
        *(float2*)(olow + tok1 + col) = make_float2(accO[nf][2] * inv1,
                                                    accO[nf][3] * inv1);
    }
}

// ============================ V projection ==================================
__global__ void vproj_kernel(const float* __restrict__ olow,
                             const float* __restrict__ V,
                             float* __restrict__ y)
{
    const int n = blockIdx.x;
    const int tid = threadIdx.x;
    __shared__ float so[128];
    so[tid] = olow[(size_t)n * RK_ + tid];
    __syncthreads();

    const int c0 = tid * 4;
    const int h  = c0 >> 6;
    const int d0 = c0 & 63;
    const float* oh = so + h * 16;

    float4 a = make_float4(0.f, 0.f, 0.f, 0.f);
    #pragma unroll
    for (int r = 0; r < 16; ++r) {
        const float ov = oh[r];
        float4 v4 = *(const float4*)(V + (size_t)((h * 16 + r) * 64 + d0));
        a.x = fmaf(ov, v4.x, a.x);
        a.y = fmaf(ov, v4.y, a.y);
        a.z = fmaf(ov, v4.z, a.z);
        a.w = fmaf(ov, v4.w, a.w);
    }
    *(float4*)(y + (size_t)n * C_ + c0) = a;
}

// ============================ launch ========================================
extern "C" void kernel_launch(void* const* d_in, const int* in_sizes, int n_in,
                              void* d_out, int out_size)
{
    const float* x    = (const float*)d_in[0];
    const float* tWq  = (const float*)d_in[3];
    const float* tWk  = (const float*)d_in[4];
    const float* tWv  = (const float*)d_in[5];
    const float* tU   = (const float*)d_in[6];
    const float* tV   = (const float*)d_in[7];
    const float* aWq  = (const float*)d_in[8];
    const float* aWk  = (const float*)d_in[9];
    const float* aWv  = (const float*)d_in[10];
    const float* aU   = (const float*)d_in[11];
    const float* aV   = (const float*)d_in[12];
    const float* ln1g = (const float*)d_in[13];
    const float* ln1b = (const float*)d_in[14];
    const float* ln2g = (const float*)d_in[15];
    const float* ln2b = (const float*)d_in[16];
    const float* ln3g = (const float*)d_in[17];
    const float* ln3b = (const float*)d_in[18];
    const float* projW= (const float*)d_in[19];
    const float* projb= (const float*)d_in[20];
    const float* gtW  = (const float*)d_in[21];
    const float* gtb  = (const float*)d_in[22];
    const float* gaW  = (const float*)d_in[23];
    const float* gab  = (const float*)d_in[24];
    float* out = (float*)d_out;

    float *xn, *yb, *x1, *x2, *qlo, *klo, *vlo, *olo;
    float *befft, *beffa, *ropec, *ropes;
    cudaGetSymbolAddress((void**)&xn,  g_xn);
    cudaGetSymbolAddress((void**)&yb,  g_y);
    cudaGetSymbolAddress((void**)&x1,  g_x1);
    cudaGetSymbolAddress((void**)&x2,  g_x2);
    cudaGetSymbolAddress((void**)&qlo, g_qlo);
    cudaGetSymbolAddress((void**)&klo, g_klo);
    cudaGetSymbolAddress((void**)&vlo, g_vlo);
    cudaGetSymbolAddress((void**)&olo, g_olo);
    cudaGetSymbolAddress((void**)&befft, g_befft);
    cudaGetSymbolAddress((void**)&beffa, g_beffa);
    cudaGetSymbolAddress((void**)&ropec, g_ropec);
    cudaGetSymbolAddress((void**)&ropes, g_ropes);

    static bool attr_set = false;
    if (!attr_set) {
        cudaFuncSetAttribute(gemm_qkv, cudaFuncAttributeMaxDynamicSharedMemorySize, GEMM_SMEM);
        cudaFuncSetAttribute(gemm_gen, cudaFuncAttributeMaxDynamicSharedMemorySize, GEMM_SMEM);
        cudaFuncSetAttribute(attn_fused<1, true>,  cudaFuncAttributeMaxDynamicSharedMemorySize, ATTN_SMEM);
        cudaFuncSetAttribute(attn_fused<4, false>, cudaFuncAttributeMaxDynamicSharedMemorySize, ATTN_SMEM);
        attr_set = true;
    }

    // -------- prep --------
    build_rope<<<32, 256>>>(ropec, ropes);
    build_beff<<<512, 128>>>(gtW, tV, befft);
    build_beff<<<512, 128>>>(gaW, aV, beffa);

    // ---------------- stage A: time attention ----------------
    ln_kernel<<<N_, 256>>>(x, ln1g, ln1b, xn);
    gemm_qkv<<<3 * (N_ / 128), 256, GEMM_SMEM>>>(xn, tWq, tWk, tWv, qlo, klo, vlo);
    attn_fused<1, true><<<dim3(B_ * L_, 8, 1), 128, ATTN_SMEM>>>(qlo, klo, vlo, tU, ropec, ropes, olo);
    vproj_kernel<<<N_, 128>>>(olo, tV, yb);
    gemm_gen<<<4 * (N_ / 128), 256, GEMM_SMEM>>>(x, 512, olo, 128, befft, gtb, x, yb, x1, 512, 640, 1);

    // ---------------- stage B: residue attention ----------------
    ln_kernel<<<N_, 256>>>(x1, ln2g, ln2b, xn);
    gemm_qkv<<<3 * (N_ / 128), 256, GEMM_SMEM>>>(xn, aWq, aWk, aWv, qlo, klo, vlo);
    attn_fused<4, false><<<dim3(B_ * T_, 8, 4), 128, ATTN_SMEM>>>(qlo, klo, vlo, aU, ropec, ropes, olo);
    vproj_kernel<<<N_, 128>>>(olo, aV, yb);
    gemm_gen<<<4 * (N_ / 128), 256, GEMM_SMEM>>>(x1, 512, olo, 128, beffa, gab, x1, yb, x2, 512, 640, 1);

    // ---------------- stage C: output projection ----------------
    ln_kernel<<<N_, 256>>>(x2, ln3g, ln3b, xn);
    gemm_gen<<<4 * (N_ / 128), 256, GEMM_SMEM>>>(xn, 512, xn, 512, projW, projb, x2, nullptr, out, 512, 512, 2);
}

// round 10
// speedup vs baseline: 1.2437x; 1.2437x over previous
#include <cuda_runtime.h>
#include <cstdint>

// ============================================================================
// ProteinSpatioTemporalAttention — round 10:
//  - round-9 GEMMs (tf32 mma, permuted-K, cp.async), Beff gate, merged QKV
//  - attention rank->head expansion moved to TENSOR CORES:
//      E = lo_tile(64x16) @ U[h]^T  via 2x m16n8k8 per 8-col group,
//      U held in 32 regs/thread, RoPE applied to C-fragments in registers,
//      Q kept entirely in registers (expansion C-frag == score A-frag under
//      the permuted-K mapping), K re-stored to smem (bank-conflict-free).
//    Old SIMT expansion (512 LDS + 512 FMA / thread / tile) deleted.
// ============================================================================

namespace {
constexpr int B_  = 4;
constexpr int T_  = 64;
constexpr int L_  = 256;
constexpr int C_  = 512;
constexpr int RK_ = 128;
constexpr int N_  = B_ * T_ * L_;   // 65536 tokens

constexpr int PAD_ = 40;            // GEMM smem row stride (floats)
constexpr int GEMM_SMEM = 2 * 2 * 128 * PAD_ * 4;   // 81920 bytes

// attention smem layout (floats)
constexpr int LOP_ = 24;                   // lo-tile row stride (bank-verified)
constexpr int QKP_ = 72;                   // ks row stride
constexpr int VP_  = 20;                   // vs row stride
constexpr int AT_LOT = 0;                  // [64][24]
constexpr int AT_KS  = AT_LOT + 64 * LOP_; // [64][72]
constexpr int AT_VS  = AT_KS + 64 * QKP_;  // [64][20]
constexpr int AT_TOT = AT_VS + 64 * VP_;   // 7424 floats
constexpr int ATTN_SMEM = AT_TOT * 4;      // 29696 bytes
}

// -------------------- scratch (device globals; no cudaMalloc) ---------------
__device__ float g_xn [N_ * C_];
__device__ float g_y  [N_ * C_];
__device__ float g_x1 [N_ * C_];
__device__ float g_x2 [N_ * C_];
__device__ float g_qlo[N_ * RK_];
__device__ float g_klo[N_ * RK_];
__device__ float g_vlo[N_ * RK_];
__device__ float g_olo[N_ * RK_];
__device__ float g_befft[512 * 640];
__device__ float g_beffa[512 * 640];
__device__ float g_ropec[256 * 32];
__device__ float g_ropes[256 * 32];

// ============================ PTX helpers ===================================
__device__ __forceinline__ uint32_t smem_u32(const void* p) {
    uint32_t a;
    asm("{ .reg .u64 t; cvta.to.shared.u64 t, %1; cvt.u32.u64 %0, t; }"
        : "=r"(a) : "l"(p));
    return a;
}
__device__ __forceinline__ uint32_t f2tf(float x) {
    uint32_t r;
    asm("cvt.rna.tf32.f32 %0, %1;" : "=r"(r) : "f"(x));
    return r;
}
__device__ __forceinline__ void mma_tf32(float* c, const uint32_t* a, const uint32_t* b) {
    asm volatile("mma.sync.aligned.m16n8k8.row.col.f32.tf32.tf32.f32 "
        "{%0,%1,%2,%3}, {%4,%5,%6,%7}, {%8,%9}, {%0,%1,%2,%3};"
        : "+f"(c[0]), "+f"(c[1]), "+f"(c[2]), "+f"(c[3])
        : "r"(a[0]), "r"(a[1]), "r"(a[2]), "r"(a[3]), "r"(b[0]), "r"(b[1]));
}
#define CP_ASYNC16(dst, src) \
    asm volatile("cp.async.cg.shared.global [%0], [%1], 16;" :: "r"(dst), "l"(src))
#define CP_COMMIT() asm volatile("cp.async.commit_group;" ::: "memory")
#define CP_WAIT1()  asm volatile("cp.async.wait_group 1;" ::: "memory")
#define CP_WAIT0()  asm volatile("cp.async.wait_group 0;" ::: "memory")

// ============================ tf32 mma GEMM body ============================
__device__ __forceinline__
void gemm_body(const float* __restrict__ A0, int lda0,
               const float* __restrict__ A1, int lda1,
               const float* __restrict__ Bw,
               const float* __restrict__ bias,
               const float* __restrict__ resid,
               const float* __restrict__ yv,
               float* __restrict__ C, int ldc,
               int K1, int Kw, int mode, int m0, int n0)
{
    extern __shared__ float sm[];
    float* As = sm;
    float* Bs = sm + 2 * 128 * PAD_;

    const int tid  = threadIdx.x;
    const int lane = tid & 31;
    const int wid  = tid >> 5;
    const int NC   = Kw >> 5;
    const int NC1  = K1 >> 5;

    const int lr = tid >> 3;
    const int lk = (tid & 7) * 4;

    const uint32_t aS0 = smem_u32(As);
    const uint32_t bS0 = smem_u32(Bs);

    auto prefetch = [&](int c, int s) {
        const float* Ap; int kb, lda;
        if (c < NC1) { Ap = A0; lda = lda0; kb = c * 32; }
        else         { Ap = A1; lda = lda1; kb = (c - NC1) * 32; }
        const uint32_t aT = aS0 + (uint32_t)(s * 128 * PAD_) * 4;
        const uint32_t bT = bS0 + (uint32_t)(s * 128 * PAD_) * 4;
        const float* srcB = Bw + (size_t)n0 * Kw + c * 32;
        #pragma unroll
        for (int it = 0; it < 4; ++it) {
            const int r = lr + it * 32;
            CP_ASYNC16(aT + (uint32_t)(r * PAD_ + lk) * 4,
                       Ap + (size_t)(m0 + r) * lda + kb + lk);
            CP_ASYNC16(bT + (uint32_t)(r * PAD_ + lk) * 4,
                       srcB + (size_t)r * Kw + lk);
        }
    };

    const int wm = (wid & 1) * 64;
    const int wn = (wid >> 1) * 32;
    const int qr = lane >> 2;
    const int tc = lane & 3;

    float acc[4][4][4];
    #pragma unroll
    for (int i = 0; i < 4; ++i)
        #pragma unroll
        for (int j = 0; j < 4; ++j)
            #pragma unroll
            for (int r = 0; r < 4; ++r) acc[i][j][r] = 0.f;

    prefetch(0, 0);
    CP_COMMIT();

    for (int c = 0; c < NC; ++c) {
        const int s = c & 1;
        if (c + 1 < NC) { prefetch(c + 1, s ^ 1); CP_COMMIT(); CP_WAIT1(); }
        else            { CP_WAIT0(); }
        __syncthreads();

        const float* a_s = As + s * 128 * PAD_ + (wm + qr) * PAD_ + 2 * tc;
        const float* b_s = Bs + s * 128 * PAD_ + (wn + qr) * PAD_ + 2 * tc;

        #pragma unroll
        for (int ks = 0; ks < 4; ++ks) {
            const int k0 = ks * 8;
            uint32_t af[4][4];
            #pragma unroll
            for (int i = 0; i < 4; ++i) {
                float2 a0 = *(const float2*)(a_s + i * 16 * PAD_ + k0);
                float2 a1 = *(const float2*)(a_s + i * 16 * PAD_ + 8 * PAD_ + k0);
                af[i][0] = f2tf(a0.x);
                af[i][1] = f2tf(a1.x);
                af[i][2] = f2tf(a0.y);
                af[i][3] = f2tf(a1.y);
            }
            #pragma unroll
            for (int j = 0; j < 4; ++j) {
                float2 bb = *(const float2*)(b_s + j * 8 * PAD_ + k0);
                uint32_t bf[2] = { f2tf(bb.x), f2tf(bb.y) };
                #pragma unroll
                for (int i = 0; i < 4; ++i) mma_tf32(acc[i][j], af[i], bf);
            }
        }
        __syncthreads();
    }

    const int row0 = m0 + wm + qr;
    const int col0 = n0 + wn + tc * 2;

    #pragma unroll
    for (int i = 0; i < 4; ++i) {
        #pragma unroll
        for (int half = 0; half < 2; ++half) {
            const int r = row0 + i * 16 + half * 8;
            float*       crow = C + (size_t)r * ldc;
            const float* rrow = resid ? resid + (size_t)r * ldc : nullptr;
            const float* yrow = yv    ? yv    + (size_t)r * ldc : nullptr;
            #pragma unroll
            for (int j = 0; j < 4; ++j) {
                const int cc = col0 + j * 8;
                float v0 = acc[i][j][half * 2 + 0];
                float v1 = acc[i][j][half * 2 + 1];
                if (mode == 0) {
                    *(float2*)(crow + cc) = make_float2(v0, v1);
                } else if (mode == 1) {
                    float2 bi = *(const float2*)(bias + cc);
                    float2 rv = *(const float2*)(rrow + cc);
                    float2 yw = *(const float2*)(yrow + cc);
                    float g0 = 1.f / (1.f + __expf(-(v0 + bi.x)));
                    float g1 = 1.f / (1.f + __expf(-(v1 + bi.y)));
                    *(float2*)(crow + cc) = make_float2(
                        g0 * rv.x + (1.f - g0) * yw.x,
                        g1 * rv.y + (1.f - g1) * yw.y);
                } else {
                    float2 bi = *(const float2*)(bias + cc);
                    float2 rv = *(const float2*)(rrow + cc);
                    *(float2*)(crow + cc) = make_float2(v0 + bi.x + rv.x,
                                                        v1 + bi.y + rv.y);
                }
            }
        }
    }
}

__global__ __launch_bounds__(256, 2)
void gemm_qkv(const float* __restrict__ A,
              const float* __restrict__ Wq, const float* __restrict__ Wk,
              const float* __restrict__ Wv,
              float* __restrict__ q, float* __restrict__ k, float* __restrict__ v)
{
    const int bx  = blockIdx.x;
    const int sel = bx % 3;
    const int m0  = (bx / 3) * 128;
    const float* Bw = (sel == 0) ? Wq : (sel == 1) ? Wk : Wv;
    float*       C  = (sel == 0) ? q  : (sel == 1) ? k  : v;
    gemm_body(A, 512, A, 512, Bw, nullptr, nullptr, nullptr, C, 128,
              512, 512, 0, m0, 0);
}

__global__ __launch_bounds__(256, 2)
void gemm_gen(const float* __restrict__ A0, int lda0,
              const float* __restrict__ A1, int lda1,
              const float* __restrict__ Bw,
              const float* __restrict__ bias,
              const float* __restrict__ resid,
              const float* __restrict__ yv,
              float* __restrict__ C, int K1, int Kw, int mode)
{
    const int bx = blockIdx.x;
    const int m0 = (bx >> 2) * 128;
    const int n0 = (bx & 3) * 128;
    gemm_body(A0, lda0, A1, lda1, Bw, bias, resid, yv, C, 512,
              K1, Kw, mode, m0, n0);
}

// ============================ prep kernels ==================================
__global__ void build_beff(const float* __restrict__ gW,
                           const float* __restrict__ V,
                           float* __restrict__ Beff)
{
    const int n = blockIdx.x;
    const int tid = threadIdx.x;
    ((float4*)(Beff + (size_t)n * 640))[tid] =
        ((const float4*)(gW + (size_t)n * 1024))[tid];
    const int h = tid >> 4, r = tid & 15;
    const float* w2 = gW + (size_t)n * 1024 + 512 + h * 64;
    const float* vr = V + (size_t)(h * 16 + r) * 64;
    float s = 0.f;
    #pragma unroll
    for (int d = 0; d < 64; ++d) s = fmaf(w2[d], vr[d], s);
    Beff[(size_t)n * 640 + 512 + tid] = s;
}

__global__ void build_rope(float* __restrict__ rc, float* __restrict__ rs)
{
    const int idx = blockIdx.x * 256 + threadIdx.x;
    const int pos = idx >> 5;
    const int ih  = idx & 31;
    const float theta = expf((float)ih * -0.28782313662425572f);
    float sn, cs;
    sincosf((float)pos * theta, &sn, &cs);
    rc[idx] = cs;  rs[idx] = sn;
}

// ============================ LayerNorm =====================================
__global__ void ln_kernel(const float* __restrict__ x,
                          const float* __restrict__ g,
                          const float* __restrict__ b,
                          float* __restrict__ out)
{
    const int n   = blockIdx.x;
    const int tid = threadIdx.x;
    const float* xr = x + (size_t)n * C_;

    float v0 = xr[tid];
    float v1 = xr[tid + 256];
    float s = v0 + v1;
    float q = v0 * v0 + v1 * v1;
    #pragma unroll
    for (int o = 16; o; o >>= 1) {
        s += __shfl_xor_sync(0xffffffffu, s, o);
        q += __shfl_xor_sync(0xffffffffu, q, o);
    }
    __shared__ float rs[8], rq[8];
    if ((tid & 31) == 0) { rs[tid >> 5] = s; rq[tid >> 5] = q; }
    __syncthreads();
    float st = 0.f, qt = 0.f;
    #pragma unroll
    for (int w = 0; w < 8; ++w) { st += rs[w]; qt += rq[w]; }

    const float mean = st * (1.f / 512.f);
    const float var  = qt * (1.f / 512.f) - mean * mean;
    const float rstd = rsqrtf(var + 1e-12f);

    float* orow = out + (size_t)n * C_;
    orow[tid]       = (v0 - mean) * rstd * g[tid]       + b[tid];
    orow[tid + 256] = (v1 - mean) * rstd * g[tid + 256] + b[tid + 256];
}

// ================= mma flash attention, tensor-core expansion ===============
// 128 threads (4 warps). Block = (sequence, head, 64-row q-tile).
// E = lo(64x16) @ U[h]^T via mma (U in regs); RoPE on C-frags in registers.
// Q stays in registers (C-frag == score A-frag); K restored to smem.
template <int KV_TILES, bool TIME>
__global__ __launch_bounds__(128)
void attn_tc(const float* __restrict__ qlo, const float* __restrict__ klo,
             const float* __restrict__ vlow, const float* __restrict__ U,
             const float* __restrict__ rc, const float* __restrict__ rs,
             float* __restrict__ olow)
{
    extern __shared__ float sm[];
    float* lot = sm + AT_LOT;   // [64][24] low-rank tile (row-major!)
    float* ks  = sm + AT_KS;    // [64][72] expanded K
    float* vs  = sm + AT_VS;    // [64][20]

    const int tid  = threadIdx.x;
    const int lane = tid & 31;
    const int w    = tid >> 5;
    const int head = blockIdx.y;

    int base, step;
    if (TIME) {
        const int b = blockIdx.x >> 8;
        const int l = blockIdx.x & 255;
        base = b * (T_ * L_) + l;  step = L_;
    } else {
        base = blockIdx.x * L_;    step = 1;
    }
    const int q0 = blockIdx.z * 64;

    const int qr = lane >> 2;
    const int c  = lane & 3;

    // ---- U[h] b-fragments in registers: ub[j][kstep][2] ----
    // B[n=d][k=r]: n = j*8+qr, k cols (2c, 2c+1) (+8 for kstep 1)
    uint32_t ub[8][2][2];
    #pragma unroll
    for (int j = 0; j < 8; ++j) {
        const float* up = U + ((size_t)head * 64 + j * 8 + qr) * 16 + 2 * c;
        float2 u0 = __ldg((const float2*)up);
        float2 u1 = __ldg((const float2*)(up + 8));
        ub[j][0][0] = f2tf(u0.x); ub[j][0][1] = f2tf(u0.y);
        ub[j][1][0] = f2tf(u1.x); ub[j][1][1] = f2tf(u1.y);
    }

    // ---- load qlo tile (row-major, no transpose) ----
    #pragma unroll
    for (int p = 0; p < 2; ++p) {
        const int idx = tid + p * 128;
        const int i = idx >> 2, r4 = (idx & 3) * 4;
        const int tok = base + (q0 + i) * step;
        *(float4*)&lot[i * LOP_ + r4] =
            *(const float4*)(qlo + (size_t)tok * RK_ + head * 16 + r4);
    }
    __syncthreads();

    // ---- expand Q via mma + register RoPE -> qa (score A-frags) ----
    uint32_t qa[8][4];
    {
        const float* a_s = lot + (w * 16 + qr) * LOP_ + 2 * c;
        float2 a00 = *(const float2*)(a_s);
        float2 a01 = *(const float2*)(a_s + 8 * LOP_);
        float2 a10 = *(const float2*)(a_s + 8);
        float2 a11 = *(const float2*)(a_s + 8 * LOP_ + 8);
        uint32_t af0[4] = { f2tf(a00.x), f2tf(a01.x), f2tf(a00.y), f2tf(a01.y) };
        uint32_t af1[4] = { f2tf(a10.x), f2tf(a11.x), f2tf(a10.y), f2tf(a11.y) };
        const int pos0 = q0 + w * 16 + qr;
        #pragma unroll
        for (int j = 0; j < 8; ++j) {
            float e[4] = {0.f, 0.f, 0.f, 0.f};
            mma_tf32(e, af0, ub[j][0]);
            mma_tf32(e, af1, ub[j][1]);
            const int ih = 4 * j + c;
            const float cs0 = __ldg(rc + pos0 * 32 + ih);
            const float sn0 = __ldg(rs + pos0 * 32 + ih);
            const float cs1 = __ldg(rc + (pos0 + 8) * 32 + ih);
            const float sn1 = __ldg(rs + (pos0 + 8) * 32 + ih);
            const float ev0 = (e[0] * cs0 - e[1] * sn0) * 0.125f;
            const float od0 = (e[0] * sn0 + e[1] * cs0) * 0.125f;
            const float ev1 = (e[2] * cs1 - e[3] * sn1) * 0.125f;
            const float od1 = (e[2] * sn1 + e[3] * cs1) * 0.125f;
            // score A-frag slots: {row qr col 2c, row qr+8 col 2c, col 2c+1 x2}
            qa[j][0] = f2tf(ev0);
            qa[j][1] = f2tf(ev1);
            qa[j][2] = f2tf(od0);
            qa[j][3] = f2tf(od1);
        }
    }
    __syncthreads();   // lot free for K tiles

    float m0v = -1e30f, m1v = -1e30f, l0v = 0.f, l1v = 0.f;
    float accO[2][4];
    #pragma unroll
    for (int nf = 0; nf < 2; ++nf)
        #pragma unroll
        for (int r = 0; r < 4; ++r) accO[nf][r] = 0.f;

    for (int kt = 0; kt < KV_TILES; ++kt) {
        // ---- load klo tile (row-major) + V tile ----
        #pragma unroll
        for (int p = 0; p < 2; ++p) {
            const int idx = tid + p * 128;
            const int i = idx >> 2, r4 = (idx & 3) * 4;
            const int tok = base + (kt * 64 + i) * step;
            *(float4*)&lot[i * LOP_ + r4] =
                *(const float4*)(klo + (size_t)tok * RK_ + head * 16 + r4);
        }
        #pragma unroll
        for (int p = 0; p < 2; ++p) {
            const int f = tid + p * 128;
            const int j = f >> 2;
            const int rq = (f & 3) * 4;
            const int tok = base + (kt * 64 + j) * step;
            *(float4*)&vs[j * VP_ + rq] =
                *(const float4*)(vlow + (size_t)tok * RK_ + head * 16 + rq);
        }
        __syncthreads();

        // ---- expand K via mma + register RoPE -> ks ----
        {
            const float* a_s = lot + (w * 16 + qr) * LOP_ + 2 * c;
            float2 a00 = *(const float2*)(a_s);
            float2 a01 = *(const float2*)(a_s + 8 * LOP_);
            float2 a10 = *(const float2*)(a_s + 8);
            float2 a11 = *(const float2*)(a_s + 8 * LOP_ + 8);
            uint32_t af0[4] = { f2tf(a00.x), f2tf(a01.x), f2tf(a00.y), f2tf(a01.y) };
            uint32_t af1[4] = { f2tf(a10.x), f2tf(a11.x), f2tf(a10.y), f2tf(a11.y) };
            const int krow = w * 16 + qr;
            const int pos0 = kt * 64 + krow;
            #pragma unroll
            for (int j = 0; j < 8; ++j) {
                float e[4] = {0.f, 0.f, 0.f, 0.f};
                mma_tf32(e, af0, ub[j][0]);
                mma_tf32(e, af1, ub[j][1]);
                const int ih = 4 * j + c;
                const float cs0 = __ldg(rc + pos0 * 32 + ih);
                const float sn0 = __ldg(rs + pos0 * 32 + ih);
                const float cs1 = __ldg(rc + (pos0 + 8) * 32 + ih);
                const float sn1 = __ldg(rs + (pos0 + 8) * 32 + ih);
                *(float2*)&ks[krow * QKP_ + j * 8 + 2 * c] =
                    make_float2(e[0] * cs0 - e[1] * sn0,
                                e[0] * sn0 + e[1] * cs0);
                *(float2*)&ks[(krow + 8) * QKP_ + j * 8 + 2 * c] =
                    make_float2(e[2] * cs1 - e[3] * sn1,
                                e[2] * sn1 + e[3] * cs1);
            }
        }
        __syncthreads();

        // ---- scores S[16 x 64] per warp via mma (A-frags in regs) ----
        float s[8][4];
        #pragma unroll
        for (int j = 0; j < 8; ++j)
            #pragma unroll
            for (int r = 0; r < 4; ++r) s[j][r] = 0.f;

        const float* b_s = ks + qr * QKP_ + 2 * c;
        #pragma unroll
        for (int ks8 = 0; ks8 < 8; ++ks8) {
            const int k0 = ks8 * 8;
            #pragma unroll
            for (int j = 0; j < 8; ++j) {
                float2 bb = *(const float2*)(b_s + j * 8 * QKP_ + k0);
                uint32_t bf[2] = { f2tf(bb.x), f2tf(bb.y) };
                mma_tf32(s[j], qa[ks8], bf);
            }
        }

        // ---- online softmax (registers + quad shuffles) ----
        float tm0 = -1e30f, tm1 = -1e30f;
        #pragma unroll
        for (int j = 0; j < 8; ++j) {
            tm0 = fmaxf(tm0, fmaxf(s[j][0], s[j][1]));
            tm1 = fmaxf(tm1, fmaxf(s[j][2], s[j][3]));
        }
        tm0 = fmaxf(tm0, __shfl_xor_sync(0xffffffffu, tm0, 1));
        tm0 = fmaxf(tm0, __shfl_xor_sync(0xffffffffu, tm0, 2));
        tm1 = fmaxf(tm1, __shfl_xor_sync(0xffffffffu, tm1, 1));
        tm1 = fmaxf(tm1, __shfl_xor_sync(0xffffffffu, tm1, 2));

        const float mn0 = fmaxf(m0v, tm0);
        const float mn1 = fmaxf(m1v, tm1);
        const float al0 = __expf(m0v - mn0);
        const float al1 = __expf(m1v - mn1);
        m0v = mn0; m1v = mn1;

        float rs0 = 0.f, rs1 = 0.f;
        #pragma unroll
        for (int j = 0; j < 8; ++j) {
            s[j][0] = __expf(s[j][0] - mn0);
            s[j][1] = __expf(s[j][1] - mn0);
            s[j][2] = __expf(s[j][2] - mn1);
            s[j][3] = __expf(s[j][3] - mn1);
            rs0 += s[j][0] + s[j][1];
            rs1 += s[j][2] + s[j][3];
        }
        rs0 += __shfl_xor_sync(0xffffffffu, rs0, 1);
        rs0 += __shfl_xor_sync(0xffffffffu, rs0, 2);
        rs1 += __shfl_xor_sync(0xffffffffu, rs1, 1);
        rs1 += __shfl_xor_sync(0xffffffffu, rs1, 2);
        l0v = l0v * al0 + rs0;
        l1v = l1v * al1 + rs1;

        #pragma unroll
        for (int nf = 0; nf < 2; ++nf) {
            accO[nf][0] *= al0; accO[nf][1] *= al0;
            accO[nf][2] *= al1; accO[nf][3] *= al1;
        }

        // ---- PV: score c-frag IS the P a-frag (permuted-K mapping) ----
        #pragma unroll
        for (int j = 0; j < 8; ++j) {
            uint32_t pa[4];
            pa[0] = f2tf(s[j][0]);
            pa[1] = f2tf(s[j][2]);
            pa[2] = f2tf(s[j][1]);
            pa[3] = f2tf(s[j][3]);
            const float* vp = vs + (j * 8 + 2 * c) * VP_;
            #pragma unroll
            for (int nf = 0; nf < 2; ++nf) {
                const int col = nf * 8 + qr;
                uint32_t bf[2] = { f2tf(vp[col]), f2tf(vp[VP_ + col]) };
                mma_tf32(accO[nf], pa, bf);
            }
        }
        __syncthreads();
    }

    // ---- epilogue ----
    const float inv0 = 1.f / l0v;
    const float inv1 = 1.f / l1v;
    const int r0 = q0 + w * 16 + qr;
    const int r1 = r0 + 8;
    const size_t tok0 = (size_t)(base + r0 * step) * RK_ + head * 16;
    const size_t tok1 = (size_t)(base + r1 * step) * RK_ + head * 16;
    #pragma unroll
    for (int nf = 0; nf < 2; ++nf) {
        const int col = nf * 8 + c * 2;
        *(float2*)(olow + tok0 + col) = make_float2(accO[nf][0] * inv0,
                                                    accO[nf][1] * inv0);
        *(float2*)(olow + tok1 + col) = make_float2(accO[nf][2] * inv1,
                                                    accO[nf][3] * inv1);
    }
}

// ============================ V projection ==================================
__global__ void vproj_kernel(const float* __restrict__ olow,
                             const float* __restrict__ V,
                             float* __restrict__ y)
{
    const int n = blockIdx.x;
    const int tid = threadIdx.x;
    __shared__ float so[128];
    so[tid] = olow[(size_t)n * RK_ + tid];
    __syncthreads();

    const int c0 = tid * 4;
    const int h  = c0 >> 6;
    const int d0 = c0 & 63;
    const float* oh = so + h * 16;

    float4 a = make_float4(0.f, 0.f, 0.f, 0.f);
    #pragma unroll
    for (int r = 0; r < 16; ++r) {
        const float ov = oh[r];
        float4 v4 = *(const float4*)(V + (size_t)((h * 16 + r) * 64 + d0));
        a.x = fmaf(ov, v4.x, a.x);
        a.y = fmaf(ov, v4.y, a.y);
        a.z = fmaf(ov, v4.z, a.z);
        a.w = fmaf(ov, v4.w, a.w);
    }
    *(float4*)(y + (size_t)n * C_ + c0) = a;
}

// ============================ launch ========================================
extern "C" void kernel_launch(void* const* d_in, const int* in_sizes, int n_in,
                              void* d_out, int out_size)
{
    const float* x    = (const float*)d_in[0];
    const float* tWq  = (const float*)d_in[3];
    const float* tWk  = (const float*)d_in[4];
    const float* tWv  = (const float*)d_in[5];
    const float* tU   = (const float*)d_in[6];
    const float* tV   = (const float*)d_in[7];
    const float* aWq  = (const float*)d_in[8];
    const float* aWk  = (const float*)d_in[9];
    const float* aWv  = (const float*)d_in[10];
    const float* aU   = (const float*)d_in[11];
    const float* aV   = (const float*)d_in[12];
    const float* ln1g = (const float*)d_in[13];
    const float* ln1b = (const float*)d_in[14];
    const float* ln2g = (const float*)d_in[15];
    const float* ln2b = (const float*)d_in[16];
    const float* ln3g = (const float*)d_in[17];
    const float* ln3b = (const float*)d_in[18];
    const float* projW= (const float*)d_in[19];
    const float* projb= (const float*)d_in[20];
    const float* gtW  = (const float*)d_in[21];
    const float* gtb  = (const float*)d_in[22];
    const float* gaW  = (const float*)d_in[23];
    const float* gab  = (const float*)d_in[24];
    float* out = (float*)d_out;

    float *xn, *yb, *x1, *x2, *qlo, *klo, *vlo, *olo;
    float *befft, *beffa, *ropec, *ropes;
    cudaGetSymbolAddress((void**)&xn,  g_xn);
    cudaGetSymbolAddress((void**)&yb,  g_y);
    cudaGetSymbolAddress((void**)&x1,  g_x1);
    cudaGetSymbolAddress((void**)&x2,  g_x2);
    cudaGetSymbolAddress((void**)&qlo, g_qlo);
    cudaGetSymbolAddress((void**)&klo, g_klo);
    cudaGetSymbolAddress((void**)&vlo, g_vlo);
    cudaGetSymbolAddress((void**)&olo, g_olo);
    cudaGetSymbolAddress((void**)&befft, g_befft);
    cudaGetSymbolAddress((void**)&beffa, g_beffa);
    cudaGetSymbolAddress((void**)&ropec, g_ropec);
    cudaGetSymbolAddress((void**)&ropes, g_ropes);

    static bool attr_set = false;
    if (!attr_set) {
        cudaFuncSetAttribute(gemm_qkv, cudaFuncAttributeMaxDynamicSharedMemorySize, GEMM_SMEM);
        cudaFuncSetAttribute(gemm_gen, cudaFuncAttributeMaxDynamicSharedMemorySize, GEMM_SMEM);
        cudaFuncSetAttribute(attn_tc<1, true>,  cudaFuncAttributeMaxDynamicSharedMemorySize, ATTN_SMEM);
        cudaFuncSetAttribute(attn_tc<4, false>, cudaFuncAttributeMaxDynamicSharedMemorySize, ATTN_SMEM);
        attr_set = true;
    }

    // -------- prep --------
    build_rope<<<32, 256>>>(ropec, ropes);
    build_beff<<<512, 128>>>(gtW, tV, befft);
    build_beff<<<512, 128>>>(gaW, aV, beffa);

    // ---------------- stage A: time attention ----------------
    ln_kernel<<<N_, 256>>>(x, ln1g, ln1b, xn);
    gemm_qkv<<<3 * (N_ / 128), 256, GEMM_SMEM>>>(xn, tWq, tWk, tWv, qlo, klo, vlo);
    attn_tc<1, true><<<dim3(B_ * L_, 8, 1), 128, ATTN_SMEM>>>(qlo, klo, vlo, tU, ropec, ropes, olo);
    vproj_kernel<<<N_, 128>>>(olo, tV, yb);
    gemm_gen<<<4 * (N_ / 128), 256, GEMM_SMEM>>>(x, 512, olo, 128, befft, gtb, x, yb, x1, 512, 640, 1);

    // ---------------- stage B: residue attention ----------------
    ln_kernel<<<N_, 256>>>(x1, ln2g, ln2b, xn);
    gemm_qkv<<<3 * (N_ / 128), 256, GEMM_SMEM>>>(xn, aWq, aWk, aWv, qlo, klo, vlo);
    attn_tc<4, false><<<dim3(B_ * T_, 8, 4), 128, ATTN_SMEM>>>(qlo, klo, vlo, aU, ropec, ropes, olo);
    vproj_kernel<<<N_, 128>>>(olo, aV, yb);
    gemm_gen<<<4 * (N_ / 128), 256, GEMM_SMEM>>>(x1, 512, olo, 128, beffa, gab, x1, yb, x2, 512, 640, 1);

    // ---------------- stage C: output projection ----------------
    ln_kernel<<<N_, 256>>>(x2, ln3g, ln3b, xn);
    gemm_gen<<<4 * (N_ / 128), 256, GEMM_SMEM>>>(xn, 512, xn, 512, projW, projb, x2, nullptr, out, 512, 512, 2);
}

// round 11
// speedup vs baseline: 1.3192x; 1.0607x over previous
#include <cuda_runtime.h>
#include <cstdint>

// ============================================================================
// ProteinSpatioTemporalAttention — round 11:
//  - LN fused into GEMM A-fragment path (stats-only kernel; ln_kernel + xn
//    buffer deleted)
//  - V-projection fused into attention epilogue via O@V mma (PV C-frag ==
//    O@V A-frag under permuted-K mapping); vproj kernel deleted
//  - round-10 GEMMs / tensor-core-expansion attention otherwise unchanged
// ============================================================================

namespace {
constexpr int B_  = 4;
constexpr int T_  = 64;
constexpr int L_  = 256;
constexpr int C_  = 512;
constexpr int RK_ = 128;
constexpr int N_  = B_ * T_ * L_;   // 65536 tokens

constexpr int PAD_ = 40;            // GEMM smem row stride (floats)
constexpr int GEMM_SMEM = 2 * 2 * 128 * PAD_ * 4;   // 81920 bytes

// attention smem layout (floats)
constexpr int LOP_ = 24;
constexpr int QKP_ = 72;
constexpr int VP_  = 20;
constexpr int AT_LOT = 0;                  // [64][24]
constexpr int AT_KS  = AT_LOT + 64 * LOP_; // [64][72]
constexpr int AT_VS  = AT_KS + 64 * QKP_;  // [64][20]
constexpr int AT_TOT = AT_VS + 64 * VP_;
constexpr int ATTN_SMEM = AT_TOT * 4;      // 29696 bytes
}

// -------------------- scratch (device globals; no cudaMalloc) ---------------
__device__ float  g_y  [N_ * C_];
__device__ float  g_x1 [N_ * C_];
__device__ float  g_x2 [N_ * C_];
__device__ float  g_qlo[N_ * RK_];
__device__ float  g_klo[N_ * RK_];
__device__ float  g_vlo[N_ * RK_];
__device__ float  g_olo[N_ * RK_];
__device__ float  g_befft[512 * 640];
__device__ float  g_beffa[512 * 640];
__device__ float  g_ropec[256 * 32];
__device__ float  g_ropes[256 * 32];
__device__ float2 g_st [N_];

// ============================ PTX helpers ===================================
__device__ __forceinline__ uint32_t smem_u32(const void* p) {
    uint32_t a;
    asm("{ .reg .u64 t; cvta.to.shared.u64 t, %1; cvt.u32.u64 %0, t; }"
        : "=r"(a) : "l"(p));
    return a;
}
__device__ __forceinline__ uint32_t f2tf(float x) {
    uint32_t r;
    asm("cvt.rna.tf32.f32 %0, %1;" : "=r"(r) : "f"(x));
    return r;
}
__device__ __forceinline__ void mma_tf32(float* c, const uint32_t* a, const uint32_t* b) {
    asm volatile("mma.sync.aligned.m16n8k8.row.col.f32.tf32.tf32.f32 "
        "{%0,%1,%2,%3}, {%4,%5,%6,%7}, {%8,%9}, {%0,%1,%2,%3};"
        : "+f"(c[0]), "+f"(c[1]), "+f"(c[2]), "+f"(c[3])
        : "r"(a[0]), "r"(a[1]), "r"(a[2]), "r"(a[3]), "r"(b[0]), "r"(b[1]));
}
#define CP_ASYNC16(dst, src) \
    asm volatile("cp.async.cg.shared.global [%0], [%1], 16;" :: "r"(dst), "l"(src))
#define CP_COMMIT() asm volatile("cp.async.commit_group;" ::: "memory")
#define CP_WAIT1()  asm volatile("cp.async.wait_group 1;" ::: "memory")
#define CP_WAIT0()  asm volatile("cp.async.wait_group 0;" ::: "memory")

// ============================ tf32 mma GEMM body ============================
// LN template: when true, A elements are normalized on fragment load using
// per-row stats (mean, rstd) and per-kcol gamma/beta (A1 must equal A0).
template <bool LN>
__device__ __forceinline__
void gemm_body(const float* __restrict__ A0, int lda0,
               const float* __restrict__ A1, int lda1,
               const float* __restrict__ Bw,
               const float* __restrict__ bias,
               const float* __restrict__ resid,
               const float* __restrict__ yv,
               float* __restrict__ C, int ldc,
               int K1, int Kw, int mode, int m0, int n0,
               const float2* __restrict__ lnst,
               const float* __restrict__ lng,
               const float* __restrict__ lnb)
{
    extern __shared__ float sm[];
    float* As = sm;
    float* Bs = sm + 2 * 128 * PAD_;

    const int tid  = threadIdx.x;
    const int lane = tid & 31;
    const int wid  = tid >> 5;
    const int NC   = Kw >> 5;
    const int NC1  = K1 >> 5;

    const int lr = tid >> 3;
    const int lk = (tid & 7) * 4;

    const uint32_t aS0 = smem_u32(As);
    const uint32_t bS0 = smem_u32(Bs);

    auto prefetch = [&](int c, int s) {
        const float* Ap; int kb, lda;
        if (c < NC1) { Ap = A0; lda = lda0; kb = c * 32; }
        else         { Ap = A1; lda = lda1; kb = (c - NC1) * 32; }
        const uint32_t aT = aS0 + (uint32_t)(s * 128 * PAD_) * 4;
        const uint32_t bT = bS0 + (uint32_t)(s * 128 * PAD_) * 4;
        const float* srcB = Bw + (size_t)n0 * Kw + c * 32;
        #pragma unroll
        for (int it = 0; it < 4; ++it) {
            const int r = lr + it * 32;
            CP_ASYNC16(aT + (uint32_t)(r * PAD_ + lk) * 4,
                       Ap + (size_t)(m0 + r) * lda + kb + lk);
            CP_ASYNC16(bT + (uint32_t)(r * PAD_ + lk) * 4,
                       srcB + (size_t)r * Kw + lk);
        }
    };

    const int wm = (wid & 1) * 64;
    const int wn = (wid >> 1) * 32;
    const int qr = lane >> 2;
    const int tc = lane & 3;

    float2 st[4][2];
    if (LN) {
        #pragma unroll
        for (int i = 0; i < 4; ++i) {
            st[i][0] = __ldg(&lnst[m0 + wm + qr + i * 16]);
            st[i][1] = __ldg(&lnst[m0 + wm + qr + i * 16 + 8]);
        }
    }

    float acc[4][4][4];
    #pragma unroll
    for (int i = 0; i < 4; ++i)
        #pragma unroll
        for (int j = 0; j < 4; ++j)
            #pragma unroll
            for (int r = 0; r < 4; ++r) acc[i][j][r] = 0.f;

    prefetch(0, 0);
    CP_COMMIT();

    for (int ch = 0; ch < NC; ++ch) {
        const int s = ch & 1;
        if (ch + 1 < NC) { prefetch(ch + 1, s ^ 1); CP_COMMIT(); CP_WAIT1(); }
        else             { CP_WAIT0(); }
        __syncthreads();

        const float* a_s = As + s * 128 * PAD_ + (wm + qr) * PAD_ + 2 * tc;
        const float* b_s = Bs + s * 128 * PAD_ + (wn + qr) * PAD_ + 2 * tc;

        #pragma unroll
        for (int ks = 0; ks < 4; ++ks) {
            const int k0 = ks * 8;
            float2 g2, b2;
            if (LN) {
                const int kcol = ch * 32 + k0 + 2 * tc;
                g2 = __ldg((const float2*)(lng + kcol));
                b2 = __ldg((const float2*)(lnb + kcol));
            }
            uint32_t af[4][4];
            #pragma unroll
            for (int i = 0; i < 4; ++i) {
                float2 a0 = *(const float2*)(a_s + i * 16 * PAD_ + k0);
                float2 a1 = *(const float2*)(a_s + i * 16 * PAD_ + 8 * PAD_ + k0);
                if (LN) {
                    a0.x = (a0.x - st[i][0].x) * st[i][0].y * g2.x + b2.x;
                    a0.y = (a0.y - st[i][0].x) * st[i][0].y * g2.y + b2.y;
                    a1.x = (a1.x - st[i][1].x) * st[i][1].y * g2.x + b2.x;
                    a1.y = (a1.y - st[i][1].x) * st[i][1].y * g2.y + b2.y;
                }
                af[i][0] = f2tf(a0.x);
                af[i][1] = f2tf(a1.x);
                af[i][2] = f2tf(a0.y);
                af[i][3] = f2tf(a1.y);
            }
            #pragma unroll
            for (int j = 0; j < 4; ++j) {
                float2 bb = *(const float2*)(b_s + j * 8 * PAD_ + k0);
                uint32_t bf[2] = { f2tf(bb.x), f2tf(bb.y) };
                #pragma unroll
                for (int i = 0; i < 4; ++i) mma_tf32(acc[i][j], af[i], bf);
            }
        }
        __syncthreads();
    }

    const int row0 = m0 + wm + qr;
    const int col0 = n0 + wn + tc * 2;

    #pragma unroll
    for (int i = 0; i < 4; ++i) {
        #pragma unroll
        for (int half = 0; half < 2; ++half) {
            const int r = row0 + i * 16 + half * 8;
            float*       crow = C + (size_t)r * ldc;
            const float* rrow = resid ? resid + (size_t)r * ldc : nullptr;
            const float* yrow = yv    ? yv    + (size_t)r * ldc : nullptr;
            #pragma unroll
            for (int j = 0; j < 4; ++j) {
                const int cc = col0 + j * 8;
                float v0 = acc[i][j][half * 2 + 0];
                float v1 = acc[i][j][half * 2 + 1];
                if (mode == 0) {
                    *(float2*)(crow + cc) = make_float2(v0, v1);
                } else if (mode == 1) {
                    float2 bi = *(const float2*)(bias + cc);
                    float2 rv = *(const float2*)(rrow + cc);
                    float2 yw = *(const float2*)(yrow + cc);
                    float g0 = 1.f / (1.f + __expf(-(v0 + bi.x)));
                    float g1 = 1.f / (1.f + __expf(-(v1 + bi.y)));
                    *(float2*)(crow + cc) = make_float2(
                        g0 * rv.x + (1.f - g0) * yw.x,
                        g1 * rv.y + (1.f - g1) * yw.y);
                } else {
                    float2 bi = *(const float2*)(bias + cc);
                    float2 rv = *(const float2*)(rrow + cc);
                    *(float2*)(crow + cc) = make_float2(v0 + bi.x + rv.x,
                                                        v1 + bi.y + rv.y);
                }
            }
        }
    }
}

// QKV with fused LN on A.
__global__ __launch_bounds__(256, 2)
void gemm_qkv(const float* __restrict__ A,
              const float2* __restrict__ lnst,
              const float* __restrict__ lng, const float* __restrict__ lnb,
              const float* __restrict__ Wq, const float* __restrict__ Wk,
              const float* __restrict__ Wv,
              float* __restrict__ q, float* __restrict__ k, float* __restrict__ v)
{
    const int bx  = blockIdx.x;
    const int sel = bx % 3;
    const int m0  = (bx / 3) * 128;
    const float* Bw = (sel == 0) ? Wq : (sel == 1) ? Wk : Wv;
    float*       C  = (sel == 0) ? q  : (sel == 1) ? k  : v;
    gemm_body<true>(A, 512, A, 512, Bw, nullptr, nullptr, nullptr, C, 128,
                    512, 512, 0, m0, 0, lnst, lng, lnb);
}

// General GEMM (N=512), optional fused LN on A.
template <bool LN>
__global__ __launch_bounds__(256, 2)
void gemm_gen(const float* __restrict__ A0, int lda0,
              const float* __restrict__ A1, int lda1,
              const float* __restrict__ Bw,
              const float* __restrict__ bias,
              const float* __restrict__ resid,
              const float* __restrict__ yv,
              float* __restrict__ C, int K1, int Kw, int mode,
              const float2* __restrict__ lnst,
              const float* __restrict__ lng, const float* __restrict__ lnb)
{
    const int bx = blockIdx.x;
    const int m0 = (bx >> 2) * 128;
    const int n0 = (bx & 3) * 128;
    gemm_body<LN>(A0, lda0, A1, lda1, Bw, bias, resid, yv, C, 512,
                  K1, Kw, mode, m0, n0, lnst, lng, lnb);
}

// ============================ prep kernels ==================================
__global__ void build_beff(const float* __restrict__ gW,
                           const float* __restrict__ V,
                           float* __restrict__ Beff)
{
    const int n = blockIdx.x;
    const int tid = threadIdx.x;
    ((float4*)(Beff + (size_t)n * 640))[tid] =
        ((const float4*)(gW + (size_t)n * 1024))[tid];
    const int h = tid >> 4, r = tid & 15;
    const float* w2 = gW + (size_t)n * 1024 + 512 + h * 64;
    const float* vr = V + (size_t)(h * 16 + r) * 64;
    float s = 0.f;
    #pragma unroll
    for (int d = 0; d < 64; ++d) s = fmaf(w2[d], vr[d], s);
    Beff[(size_t)n * 640 + 512 + tid] = s;
}

__global__ void build_rope(float* __restrict__ rc, float* __restrict__ rs)
{
    const int idx = blockIdx.x * 256 + threadIdx.x;
    const int pos = idx >> 5;
    const int ih  = idx & 31;
    const float theta = expf((float)ih * -0.28782313662425572f);
    float sn, cs;
    sincosf((float)pos * theta, &sn, &cs);
    rc[idx] = cs;  rs[idx] = sn;
}

// ===================== LN stats (mean, rstd per token) ======================
__global__ void ln_stats(const float* __restrict__ x, float2* __restrict__ st)
{
    const int tok  = blockIdx.x * 8 + (threadIdx.x >> 5);
    const int lane = threadIdx.x & 31;
    const float4* xr = (const float4*)(x + (size_t)tok * C_);
    float s = 0.f, q = 0.f;
    #pragma unroll
    for (int p = 0; p < 4; ++p) {
        float4 v = xr[lane + p * 32];
        s += v.x + v.y + v.z + v.w;
        q += v.x * v.x + v.y * v.y + v.z * v.z + v.w * v.w;
    }
    #pragma unroll
    for (int o = 16; o; o >>= 1) {
        s += __shfl_xor_sync(0xffffffffu, s, o);
        q += __shfl_xor_sync(0xffffffffu, q, o);
    }
    if (lane == 0) {
        const float mean = s * (1.f / 512.f);
        const float var  = q * (1.f / 512.f) - mean * mean;
        st[tok] = make_float2(mean, rsqrtf(var + 1e-12f));
    }
}

// ================= mma flash attention, TC expansion + fused O@V ============
template <int KV_TILES, bool TIME>
__global__ __launch_bounds__(128)
void attn_tc(const float* __restrict__ qlo, const float* __restrict__ klo,
             const float* __restrict__ vlow, const float* __restrict__ U,
             const float* __restrict__ Vw,
             const float* __restrict__ rc, const float* __restrict__ rs,
             float* __restrict__ olow, float* __restrict__ y)
{
    extern __shared__ float sm[];
    float* lot = sm + AT_LOT;   // [64][24]
    float* ks  = sm + AT_KS;    // [64][72]
    float* vs  = sm + AT_VS;    // [64][20]

    const int tid  = threadIdx.x;
    const int lane = tid & 31;
    const int w    = tid >> 5;
    const int head = blockIdx.y;

    int base, step;
    if (TIME) {
        const int b = blockIdx.x >> 8;
        const int l = blockIdx.x & 255;
        base = b * (T_ * L_) + l;  step = L_;
    } else {
        base = blockIdx.x * L_;    step = 1;
    }
    const int q0 = blockIdx.z * 64;

    const int qr = lane >> 2;
    const int c  = lane & 3;

    // ---- U[h] b-fragments in registers ----
    uint32_t ub[8][2][2];
    #pragma unroll
    for (int j = 0; j < 8; ++j) {
        const float* up = U + ((size_t)head * 64 + j * 8 + qr) * 16 + 2 * c;
        float2 u0 = __ldg((const float2*)up);
        float2 u1 = __ldg((const float2*)(up + 8));
        ub[j][0][0] = f2tf(u0.x); ub[j][0][1] = f2tf(u0.y);
        ub[j][1][0] = f2tf(u1.x); ub[j][1][1] = f2tf(u1.y);
    }

    // ---- load qlo tile ----
    #pragma unroll
    for (int p = 0; p < 2; ++p) {
        const int idx = tid + p * 128;
        const int i = idx >> 2, r4 = (idx & 3) * 4;
        const int tok = base + (q0 + i) * step;
        *(float4*)&lot[i * LOP_ + r4] =
            *(const float4*)(qlo + (size_t)tok * RK_ + head * 16 + r4);
    }
    __syncthreads();

    // ---- expand Q via mma + register RoPE -> qa ----
    uint32_t qa[8][4];
    {
        const float* a_s = lot + (w * 16 + qr) * LOP_ + 2 * c;
        float2 a00 = *(const float2*)(a_s);
        float2 a01 = *(const float2*)(a_s + 8 * LOP_);
        float2 a10 = *(const float2*)(a_s + 8);
        float2 a11 = *(const float2*)(a_s + 8 * LOP_ + 8);
        uint32_t af0[4] = { f2tf(a00.x), f2tf(a01.x), f2tf(a00.y), f2tf(a01.y) };
        uint32_t af1[4] = { f2tf(a10.x), f2tf(a11.x), f2tf(a10.y), f2tf(a11.y) };
        const int pos0 = q0 + w * 16 + qr;
        #pragma unroll
        for (int j = 0; j < 8; ++j) {
            float e[4] = {0.f, 0.f, 0.f, 0.f};
            mma_tf32(e, af0, ub[j][0]);
            mma_tf32(e, af1, ub[j][1]);
            const int ih = 4 * j + c;
            const float cs0 = __ldg(rc + pos0 * 32 + ih);
            const float sn0 = __ldg(rs + pos0 * 32 + ih);
            const float cs1 = __ldg(rc + (pos0 + 8) * 32 + ih);
            const float sn1 = __ldg(rs + (pos0 + 8) * 32 + ih);
            qa[j][0] = f2tf((e[0] * cs0 - e[1] * sn0) * 0.125f);
            qa[j][1] = f2tf((e[2] * cs1 - e[3] * sn1) * 0.125f);
            qa[j][2] = f2tf((e[0] * sn0 + e[1] * cs0) * 0.125f);
            qa[j][3] = f2tf((e[2] * sn1 + e[3] * cs1) * 0.125f);
        }
    }
    __syncthreads();

    float m0v = -1e30f, m1v = -1e30f, l0v = 0.f, l1v = 0.f;
    float accO[2][4];
    #pragma unroll
    for (int nf = 0; nf < 2; ++nf)
        #pragma unroll
        for (int r = 0; r < 4; ++r) accO[nf][r] = 0.f;

    for (int kt = 0; kt < KV_TILES; ++kt) {
        // ---- load klo tile + V tile ----
        #pragma unroll
        for (int p = 0; p < 2; ++p) {
            const int idx = tid + p * 128;
            const int i = idx >> 2, r4 = (idx & 3) * 4;
            const int tok = base + (kt * 64 + i) * step;
            *(float4*)&lot[i * LOP_ + r4] =
                *(const float4*)(klo + (size_t)tok * RK_ + head * 16 + r4);
        }
        #pragma unroll
        for (int p = 0; p < 2; ++p) {
            const int f = tid + p * 128;
            const int j = f >> 2;
            const int rq = (f & 3) * 4;
            const int tok = base + (kt * 64 + j) * step;
            *(float4*)&vs[j * VP_ + rq] =
                *(const float4*)(vlow + (size_t)tok * RK_ + head * 16 + rq);
        }
        __syncthreads();

        // ---- expand K via mma + register RoPE -> ks ----
        {
            const float* a_s = lot + (w * 16 + qr) * LOP_ + 2 * c;
            float2 a00 = *(const float2*)(a_s);
            float2 a01 = *(const float2*)(a_s + 8 * LOP_);
            float2 a10 = *(const float2*)(a_s + 8);
            float2 a11 = *(const float2*)(a_s + 8 * LOP_ + 8);
            uint32_t af0[4] = { f2tf(a00.x), f2tf(a01.x), f2tf(a00.y), f2tf(a01.y) };
            uint32_t af1[4] = { f2tf(a10.x), f2tf(a11.x), f2tf(a10.y), f2tf(a11.y) };
            const int krow = w * 16 + qr;
            const int pos0 = kt * 64 + krow;
            #pragma unroll
            for (int j = 0; j < 8; ++j) {
                float e[4] = {0.f, 0.f, 0.f, 0.f};
                mma_tf32(e, af0, ub[j][0]);
                mma_tf32(e, af1, ub[j][1]);
                const int ih = 4 * j + c;
                const float cs0 = __ldg(rc + pos0 * 32 + ih);
                const float sn0 = __ldg(rs + pos0 * 32 + ih);
                const float cs1 = __ldg(rc + (pos0 + 8) * 32 + ih);
                const float sn1 = __ldg(rs + (pos0 + 8) * 32 + ih);
                *(float2*)&ks[krow * QKP_ + j * 8 + 2 * c] =
                    make_float2(e[0] * cs0 - e[1] * sn0,
                                e[0] * sn0 + e[1] * cs0);
                *(float2*)&ks[(krow + 8) * QKP_ + j * 8 + 2 * c] =
                    make_float2(e[2] * cs1 - e[3] * sn1,
                                e[2] * sn1 + e[3] * cs1);
            }
        }
        __syncthreads();

        // ---- scores via mma (A-frags in regs) ----
        float s[8][4];
        #pragma unroll
        for (int j = 0; j < 8; ++j)
            #pragma unroll
            for (int r = 0; r < 4; ++r) s[j][r] = 0.f;

        const float* b_s = ks + qr * QKP_ + 2 * c;
        #pragma unroll
        for (int ks8 = 0; ks8 < 8; ++ks8) {
            const int k0 = ks8 * 8;
            #pragma unroll
            for (int j = 0; j < 8; ++j) {
                float2 bb = *(const float2*)(b_s + j * 8 * QKP_ + k0);
                uint32_t bf[2] = { f2tf(bb.x), f2tf(bb.y) };
                mma_tf32(s[j], qa[ks8], bf);
            }
        }

        // ---- online softmax ----
        float tm0 = -1e30f, tm1 = -1e30f;
        #pragma unroll
        for (int j = 0; j < 8; ++j) {
            tm0 = fmaxf(tm0, fmaxf(s[j][0], s[j][1]));
            tm1 = fmaxf(tm1, fmaxf(s[j][2], s[j][3]));
        }
        tm0 = fmaxf(tm0, __shfl_xor_sync(0xffffffffu, tm0, 1));
        tm0 = fmaxf(tm0, __shfl_xor_sync(0xffffffffu, tm0, 2));
        tm1 = fmaxf(tm1, __shfl_xor_sync(0xffffffffu, tm1, 1));
        tm1 = fmaxf(tm1, __shfl_xor_sync(0xffffffffu, tm1, 2));

        const float mn0 = fmaxf(m0v, tm0);
        const float mn1 = fmaxf(m1v, tm1);
        const float al0 = __expf(m0v - mn0);
        const float al1 = __expf(m1v - mn1);
        m0v = mn0; m1v = mn1;

        float rs0 = 0.f, rs1 = 0.f;
        #pragma unroll
        for (int j = 0; j < 8; ++j) {
            s[j][0] = __expf(s[j][0] - mn0);
            s[j][1] = __expf(s[j][1] - mn0);
            s[j][2] = __expf(s[j][2] - mn1);
            s[j][3] = __expf(s[j][3] - mn1);
            rs0 += s[j][0] + s[j][1];
            rs1 += s[j][2] + s[j][3];
        }
        rs0 += __shfl_xor_sync(0xffffffffu, rs0, 1);
        rs0 += __shfl_xor_sync(0xffffffffu, rs0, 2);
        rs1 += __shfl_xor_sync(0xffffffffu, rs1, 1);
        rs1 += __shfl_xor_sync(0xffffffffu, rs1, 2);
        l0v = l0v * al0 + rs0;
        l1v = l1v * al1 + rs1;

        #pragma unroll
        for (int nf = 0; nf < 2; ++nf) {
            accO[nf][0] *= al0; accO[nf][1] *= al0;
            accO[nf][2] *= al1; accO[nf][3] *= al1;
        }

        // ---- PV (shuffle-free) ----
        #pragma unroll
        for (int j = 0; j < 8; ++j) {
            uint32_t pa[4];
            pa[0] = f2tf(s[j][0]);
            pa[1] = f2tf(s[j][2]);
            pa[2] = f2tf(s[j][1]);
            pa[3] = f2tf(s[j][3]);
            const float* vp = vs + (j * 8 + 2 * c) * VP_;
            #pragma unroll
            for (int nf = 0; nf < 2; ++nf) {
                const int col = nf * 8 + qr;
                uint32_t bf[2] = { f2tf(vp[col]), f2tf(vp[VP_ + col]) };
                mma_tf32(accO[nf], pa, bf);
            }
        }
        __syncthreads();
    }

    // ---- epilogue: normalize, store olow, fused y = O @ V[h] ----
    const float inv0 = 1.f / l0v;
    const float inv1 = 1.f / l1v;
    const int r0 = q0 + w * 16 + qr;
    const int r1 = r0 + 8;
    const size_t tok0 = (size_t)(base + r0 * step);
    const size_t tok1 = (size_t)(base + r1 * step);

    #pragma unroll
    for (int nf = 0; nf < 2; ++nf) {
        const int col = nf * 8 + c * 2;
        *(float2*)(olow + tok0 * RK_ + head * 16 + col) =
            make_float2(accO[nf][0] * inv0, accO[nf][1] * inv0);
        *(float2*)(olow + tok1 * RK_ + head * 16 + col) =
            make_float2(accO[nf][2] * inv1, accO[nf][3] * inv1);
    }

    // O@V: PV C-frag (normalized) == A-frag under permuted-K mapping
    uint32_t oa[2][4];
    #pragma unroll
    for (int s2 = 0; s2 < 2; ++s2) {
        oa[s2][0] = f2tf(accO[s2][0] * inv0);
        oa[s2][1] = f2tf(accO[s2][2] * inv1);
        oa[s2][2] = f2tf(accO[s2][1] * inv0);
        oa[s2][3] = f2tf(accO[s2][3] * inv1);
    }
    const float* Vh = Vw + (size_t)head * 1024;   // V[h]: [16 r][64 d]
    #pragma unroll
    for (int j = 0; j < 8; ++j) {
        float ya[4] = {0.f, 0.f, 0.f, 0.f};
        #pragma unroll
        for (int s2 = 0; s2 < 2; ++s2) {
            const int rr = s2 * 8 + 2 * c;
            uint32_t bf[2] = { f2tf(__ldg(Vh + rr * 64 + j * 8 + qr)),
                               f2tf(__ldg(Vh + (rr + 1) * 64 + j * 8 + qr)) };
            mma_tf32(ya, oa[s2], bf);
        }
        const int dcol = head * 64 + j * 8 + 2 * c;
        *(float2*)(y + tok0 * C_ + dcol) = make_float2(ya[0], ya[1]);
        *(float2*)(y + tok1 * C_ + dcol) = make_float2(ya[2], ya[3]);
    }
}

// ============================ launch ========================================
extern "C" void kernel_launch(void* const* d_in, const int* in_sizes, int n_in,
                              void* d_out, int out_size)
{
    const float* x    = (const float*)d_in[0];
    const float* tWq  = (const float*)d_in[3];
    const float* tWk  = (const float*)d_in[4];
    const float* tWv  = (const float*)d_in[5];
    const float* tU   = (const float*)d_in[6];
    const float* tV   = (const float*)d_in[7];
    const float* aWq  = (const float*)d_in[8];
    const float* aWk  = (const float*)d_in[9];
    const float* aWv  = (const float*)d_in[10];
    const float* aU   = (const float*)d_in[11];
    const float* aV   = (const float*)d_in[12];
    const float* ln1g = (const float*)d_in[13];
    const float* ln1b = (const float*)d_in[14];
    const float* ln2g = (const float*)d_in[15];
    const float* ln2b = (const float*)d_in[16];
    const float* ln3g = (const float*)d_in[17];
    const float* ln3b = (const float*)d_in[18];
    const float* projW= (const float*)d_in[19];
    const float* projb= (const float*)d_in[20];
    const float* gtW  = (const float*)d_in[21];
    const float* gtb  = (const float*)d_in[22];
    const float* gaW  = (const float*)d_in[23];
    const float* gab  = (const float*)d_in[24];
    float* out = (float*)d_out;

    float *yb, *x1, *x2, *qlo, *klo, *vlo, *olo;
    float *befft, *beffa, *ropec, *ropes;
    float2* stp;
    cudaGetSymbolAddress((void**)&yb,  g_y);
    cudaGetSymbolAddress((void**)&x1,  g_x1);
    cudaGetSymbolAddress((void**)&x2,  g_x2);
    cudaGetSymbolAddress((void**)&qlo, g_qlo);
    cudaGetSymbolAddress((void**)&klo, g_klo);
    cudaGetSymbolAddress((void**)&vlo, g_vlo);
    cudaGetSymbolAddress((void**)&olo, g_olo);
    cudaGetSymbolAddress((void**)&befft, g_befft);
    cudaGetSymbolAddress((void**)&beffa, g_beffa);
    cudaGetSymbolAddress((void**)&ropec, g_ropec);
    cudaGetSymbolAddress((void**)&ropes, g_ropes);
    cudaGetSymbolAddress((void**)&stp,  g_st);

    static bool attr_set = false;
    if (!attr_set) {
        cudaFuncSetAttribute(gemm_qkv, cudaFuncAttributeMaxDynamicSharedMemorySize, GEMM_SMEM);
        cudaFuncSetAttribute(gemm_gen<false>, cudaFuncAttributeMaxDynamicSharedMemorySize, GEMM_SMEM);
        cudaFuncSetAttribute(gemm_gen<true>,  cudaFuncAttributeMaxDynamicSharedMemorySize, GEMM_SMEM);
        cudaFuncSetAttribute(attn_tc<1, true>,  cudaFuncAttributeMaxDynamicSharedMemorySize, ATTN_SMEM);
        cudaFuncSetAttribute(attn_tc<4, false>, cudaFuncAttributeMaxDynamicSharedMemorySize, ATTN_SMEM);
        attr_set = true;
    }

    // -------- prep --------
    build_rope<<<32, 256>>>(ropec, ropes);
    build_beff<<<512, 128>>>(gtW, tV, befft);
    build_beff<<<512, 128>>>(gaW, aV, beffa);

    // ---------------- stage A: time attention ----------------
    ln_stats<<<N_ / 8, 256>>>(x, stp);
    gemm_qkv<<<3 * (N_ / 128), 256, GEMM_SMEM>>>(x, stp, ln1g, ln1b,
                                                 tWq, tWk, tWv, qlo, klo, vlo);
    attn_tc<1, true><<<dim3(B_ * L_, 8, 1), 128, ATTN_SMEM>>>(
        qlo, klo, vlo, tU, tV, ropec, ropes, olo, yb);
    gemm_gen<false><<<4 * (N_ / 128), 256, GEMM_SMEM>>>(
        x, 512, olo, 128, befft, gtb, x, yb, x1, 512, 640, 1,
        nullptr, nullptr, nullptr);

    // ---------------- stage B: residue attention ----------------
    ln_stats<<<N_ / 8, 256>>>(x1, stp);
    gemm_qkv<<<3 * (N_ / 128), 256, GEMM_SMEM>>>(x1, stp, ln2g, ln2b,
                                                 aWq, aWk, aWv, qlo, klo, vlo);
    attn_tc<4, false><<<dim3(B_ * T_, 8, 4), 128, ATTN_SMEM>>>(
        qlo, klo, vlo, aU, aV, ropec, ropes, olo, yb);
    gemm_gen<false><<<4 * (N_ / 128), 256, GEMM_SMEM>>>(
        x1, 512, olo, 128, beffa, gab, x1, yb, x2, 512, 640, 1,
        nullptr, nullptr, nullptr);

    // ---------------- stage C: output projection ----------------
    ln_stats<<<N_ / 8, 256>>>(x2, stp);
    gemm_gen<true><<<4 * (N_ / 128), 256, GEMM_SMEM>>>(
        x2, 512, x2, 512, projW, projb, x2, nullptr, out, 512, 512, 2,
        stp, ln3g, ln3b);
}

// round 12
// speedup vs baseline: 1.4649x; 1.1105x over previous
#include <cuda_runtime.h>
#include <cstdint>

// ============================================================================
// ProteinSpatioTemporalAttention — round 12:
//  - GEMM mainloop feeds raw fp32 bits to mma.tf32 (HW truncation) — deletes
//    ~96 cvt.rna per warp per K-chunk from the issue stream / LDS->mma chain.
//    Attention keeps cvt.rna (error-budget isolation).
//  - otherwise identical to round 11 (LN fused in GEMM, O@V fused in attn).
// ============================================================================

namespace {
constexpr int B_  = 4;
constexpr int T_  = 64;
constexpr int L_  = 256;
constexpr int C_  = 512;
constexpr int RK_ = 128;
constexpr int N_  = B_ * T_ * L_;   // 65536 tokens

constexpr int PAD_ = 40;            // GEMM smem row stride (floats)
constexpr int GEMM_SMEM = 2 * 2 * 128 * PAD_ * 4;   // 81920 bytes

// attention smem layout (floats)
constexpr int LOP_ = 24;
constexpr int QKP_ = 72;
constexpr int VP_  = 20;
constexpr int AT_LOT = 0;                  // [64][24]
constexpr int AT_KS  = AT_LOT + 64 * LOP_; // [64][72]
constexpr int AT_VS  = AT_KS + 64 * QKP_;  // [64][20]
constexpr int AT_TOT = AT_VS + 64 * VP_;
constexpr int ATTN_SMEM = AT_TOT * 4;      // 29696 bytes
}

// -------------------- scratch (device globals; no cudaMalloc) ---------------
__device__ float  g_y  [N_ * C_];
__device__ float  g_x1 [N_ * C_];
__device__ float  g_x2 [N_ * C_];
__device__ float  g_qlo[N_ * RK_];
__device__ float  g_klo[N_ * RK_];
__device__ float  g_vlo[N_ * RK_];
__device__ float  g_olo[N_ * RK_];
__device__ float  g_befft[512 * 640];
__device__ float  g_beffa[512 * 640];
__device__ float  g_ropec[256 * 32];
__device__ float  g_ropes[256 * 32];
__device__ float2 g_st [N_];

// ============================ PTX helpers ===================================
__device__ __forceinline__ uint32_t smem_u32(const void* p) {
    uint32_t a;
    asm("{ .reg .u64 t; cvta.to.shared.u64 t, %1; cvt.u32.u64 %0, t; }"
        : "=r"(a) : "l"(p));
    return a;
}
__device__ __forceinline__ uint32_t f2tf(float x) {   // round-to-nearest tf32
    uint32_t r;
    asm("cvt.rna.tf32.f32 %0, %1;" : "=r"(r) : "f"(x));
    return r;
}
__device__ __forceinline__ uint32_t f2raw(float x) {  // raw bits (HW truncates)
    return __float_as_uint(x);
}
__device__ __forceinline__ void mma_tf32(float* c, const uint32_t* a, const uint32_t* b) {
    asm volatile("mma.sync.aligned.m16n8k8.row.col.f32.tf32.tf32.f32 "
        "{%0,%1,%2,%3}, {%4,%5,%6,%7}, {%8,%9}, {%0,%1,%2,%3};"
        : "+f"(c[0]), "+f"(c[1]), "+f"(c[2]), "+f"(c[3])
        : "r"(a[0]), "r"(a[1]), "r"(a[2]), "r"(a[3]), "r"(b[0]), "r"(b[1]));
}
#define CP_ASYNC16(dst, src) \
    asm volatile("cp.async.cg.shared.global [%0], [%1], 16;" :: "r"(dst), "l"(src))
#define CP_COMMIT() asm volatile("cp.async.commit_group;" ::: "memory")
#define CP_WAIT1()  asm volatile("cp.async.wait_group 1;" ::: "memory")
#define CP_WAIT0()  asm volatile("cp.async.wait_group 0;" ::: "memory")

// ============================ tf32 mma GEMM body ============================
template <bool LN>
__device__ __forceinline__
void gemm_body(const float* __restrict__ A0, int lda0,
               const float* __restrict__ A1, int lda1,
               const float* __restrict__ Bw,
               const float* __restrict__ bias,
               const float* __restrict__ resid,
               const float* __restrict__ yv,
               float* __restrict__ C, int ldc,
               int K1, int Kw, int mode, int m0, int n0,
               const float2* __restrict__ lnst,
               const float* __restrict__ lng,
               const float* __restrict__ lnb)
{
    extern __shared__ float sm[];
    float* As = sm;
    float* Bs = sm + 2 * 128 * PAD_;

    const int tid  = threadIdx.x;
    const int lane = tid & 31;
    const int wid  = tid >> 5;
    const int NC   = Kw >> 5;
    const int NC1  = K1 >> 5;

    const int lr = tid >> 3;
    const int lk = (tid & 7) * 4;

    const uint32_t aS0 = smem_u32(As);
    const uint32_t bS0 = smem_u32(Bs);

    auto prefetch = [&](int c, int s) {
        const float* Ap; int kb, lda;
        if (c < NC1) { Ap = A0; lda = lda0; kb = c * 32; }
        else         { Ap = A1; lda = lda1; kb = (c - NC1) * 32; }
        const uint32_t aT = aS0 + (uint32_t)(s * 128 * PAD_) * 4;
        const uint32_t bT = bS0 + (uint32_t)(s * 128 * PAD_) * 4;
        const float* srcB = Bw + (size_t)n0 * Kw + c * 32;
        #pragma unroll
        for (int it = 0; it < 4; ++it) {
            const int r = lr + it * 32;
            CP_ASYNC16(aT + (uint32_t)(r * PAD_ + lk) * 4,
                       Ap + (size_t)(m0 + r) * lda + kb + lk);
            CP_ASYNC16(bT + (uint32_t)(r * PAD_ + lk) * 4,
                       srcB + (size_t)r * Kw + lk);
        }
    };

    const int wm = (wid & 1) * 64;
    const int wn = (wid >> 1) * 32;
    const int qr = lane >> 2;
    const int tc = lane & 3;

    float2 st[4][2];
    if (LN) {
        #pragma unroll
        for (int i = 0; i < 4; ++i) {
            st[i][0] = __ldg(&lnst[m0 + wm + qr + i * 16]);
            st[i][1] = __ldg(&lnst[m0 + wm + qr + i * 16 + 8]);
        }
    }

    float acc[4][4][4];
    #pragma unroll
    for (int i = 0; i < 4; ++i)
        #pragma unroll
        for (int j = 0; j < 4; ++j)
            #pragma unroll
            for (int r = 0; r < 4; ++r) acc[i][j][r] = 0.f;

    prefetch(0, 0);
    CP_COMMIT();

    for (int ch = 0; ch < NC; ++ch) {
        const int s = ch & 1;
        if (ch + 1 < NC) { prefetch(ch + 1, s ^ 1); CP_COMMIT(); CP_WAIT1(); }
        else             { CP_WAIT0(); }
        __syncthreads();

        const float* a_s = As + s * 128 * PAD_ + (wm + qr) * PAD_ + 2 * tc;
        const float* b_s = Bs + s * 128 * PAD_ + (wn + qr) * PAD_ + 2 * tc;

        #pragma unroll
        for (int ks = 0; ks < 4; ++ks) {
            const int k0 = ks * 8;
            float2 g2, b2;
            if (LN) {
                const int kcol = ch * 32 + k0 + 2 * tc;
                g2 = __ldg((const float2*)(lng + kcol));
                b2 = __ldg((const float2*)(lnb + kcol));
            }
            uint32_t af[4][4];
            #pragma unroll
            for (int i = 0; i < 4; ++i) {
                float2 a0 = *(const float2*)(a_s + i * 16 * PAD_ + k0);
                float2 a1 = *(const float2*)(a_s + i * 16 * PAD_ + 8 * PAD_ + k0);
                if (LN) {
                    a0.x = (a0.x - st[i][0].x) * st[i][0].y * g2.x + b2.x;
                    a0.y = (a0.y - st[i][0].x) * st[i][0].y * g2.y + b2.y;
                    a1.x = (a1.x - st[i][1].x) * st[i][1].y * g2.x + b2.x;
                    a1.y = (a1.y - st[i][1].x) * st[i][1].y * g2.y + b2.y;
                }
                af[i][0] = f2raw(a0.x);
                af[i][1] = f2raw(a1.x);
                af[i][2] = f2raw(a0.y);
                af[i][3] = f2raw(a1.y);
            }
            #pragma unroll
            for (int j = 0; j < 4; ++j) {
                float2 bb = *(const float2*)(b_s + j * 8 * PAD_ + k0);
                uint32_t bf[2] = { f2raw(bb.x), f2raw(bb.y) };
                #pragma unroll
                for (int i = 0; i < 4; ++i) mma_tf32(acc[i][j], af[i], bf);
            }
        }
        __syncthreads();
    }

    const int row0 = m0 + wm + qr;
    const int col0 = n0 + wn + tc * 2;

    #pragma unroll
    for (int i = 0; i < 4; ++i) {
        #pragma unroll
        for (int half = 0; half < 2; ++half) {
            const int r = row0 + i * 16 + half * 8;
            float*       crow = C + (size_t)r * ldc;
            const float* rrow = resid ? resid + (size_t)r * ldc : nullptr;
            const float* yrow = yv    ? yv    + (size_t)r * ldc : nullptr;
            #pragma unroll
            for (int j = 0; j < 4; ++j) {
                const int cc = col0 + j * 8;
                float v0 = acc[i][j][half * 2 + 0];
                float v1 = acc[i][j][half * 2 + 1];
                if (mode == 0) {
                    *(float2*)(crow + cc) = make_float2(v0, v1);
                } else if (mode == 1) {
                    float2 bi = *(const float2*)(bias + cc);
                    float2 rv = *(const float2*)(rrow + cc);
                    float2 yw = *(const float2*)(yrow + cc);
                    float g0 = 1.f / (1.f + __expf(-(v0 + bi.x)));
                    float g1 = 1.f / (1.f + __expf(-(v1 + bi.y)));
                    *(float2*)(crow + cc) = make_float2(
                        g0 * rv.x + (1.f - g0) * yw.x,
                        g1 * rv.y + (1.f - g1) * yw.y);
                } else {
                    float2 bi = *(const float2*)(bias + cc);
                    float2 rv = *(const float2*)(rrow + cc);
                    *(float2*)(crow + cc) = make_float2(v0 + bi.x + rv.x,
                                                        v1 + bi.y + rv.y);
                }
            }
        }
    }
}

// QKV with fused LN on A.
__global__ __launch_bounds__(256, 2)
void gemm_qkv(const float* __restrict__ A,
              const float2* __restrict__ lnst,
              const float* __restrict__ lng, const float* __restrict__ lnb,
              const float* __restrict__ Wq, const float* __restrict__ Wk,
              const float* __restrict__ Wv,
              float* __restrict__ q, float* __restrict__ k, float* __restrict__ v)
{
    const int bx  = blockIdx.x;
    const int sel = bx % 3;
    const int m0  = (bx / 3) * 128;
    const float* Bw = (sel == 0) ? Wq : (sel == 1) ? Wk : Wv;
    float*       C  = (sel == 0) ? q  : (sel == 1) ? k  : v;
    gemm_body<true>(A, 512, A, 512, Bw, nullptr, nullptr, nullptr, C, 128,
                    512, 512, 0, m0, 0, lnst, lng, lnb);
}

template <bool LN>
__global__ __launch_bounds__(256, 2)
void gemm_gen(const float* __restrict__ A0, int lda0,
              const float* __restrict__ A1, int lda1,
              const float* __restrict__ Bw,
              const float* __restrict__ bias,
              const float* __restrict__ resid,
              const float* __restrict__ yv,
              float* __restrict__ C, int K1, int Kw, int mode,
              const float2* __restrict__ lnst,
              const float* __restrict__ lng, const float* __restrict__ lnb)
{
    const int bx = blockIdx.x;
    const int m0 = (bx >> 2) * 128;
    const int n0 = (bx & 3) * 128;
    gemm_body<LN>(A0, lda0, A1, lda1, Bw, bias, resid, yv, C, 512,
                  K1, Kw, mode, m0, n0, lnst, lng, lnb);
}

// ============================ prep kernels ==================================
__global__ void build_beff(const float* __restrict__ gW,
                           const float* __restrict__ V,
                           float* __restrict__ Beff)
{
    const int n = blockIdx.x;
    const int tid = threadIdx.x;
    ((float4*)(Beff + (size_t)n * 640))[tid] =
        ((const float4*)(gW + (size_t)n * 1024))[tid];
    const int h = tid >> 4, r = tid & 15;
    const float* w2 = gW + (size_t)n * 1024 + 512 + h * 64;
    const float* vr = V + (size_t)(h * 16 + r) * 64;
    float s = 0.f;
    #pragma unroll
    for (int d = 0; d < 64; ++d) s = fmaf(w2[d], vr[d], s);
    Beff[(size_t)n * 640 + 512 + tid] = s;
}

__global__ void build_rope(float* __restrict__ rc, float* __restrict__ rs)
{
    const int idx = blockIdx.x * 256 + threadIdx.x;
    const int pos = idx >> 5;
    const int ih  = idx & 31;
    const float theta = expf((float)ih * -0.28782313662425572f);
    float sn, cs;
    sincosf((float)pos * theta, &sn, &cs);
    rc[idx] = cs;  rs[idx] = sn;
}

// ===================== LN stats (mean, rstd per token) ======================
__global__ void ln_stats(const float* __restrict__ x, float2* __restrict__ st)
{
    const int tok  = blockIdx.x * 8 + (threadIdx.x >> 5);
    const int lane = threadIdx.x & 31;
    const float4* xr = (const float4*)(x + (size_t)tok * C_);
    float s = 0.f, q = 0.f;
    #pragma unroll
    for (int p = 0; p < 4; ++p) {
        float4 v = xr[lane + p * 32];
        s += v.x + v.y + v.z + v.w;
        q += v.x * v.x + v.y * v.y + v.z * v.z + v.w * v.w;
    }
    #pragma unroll
    for (int o = 16; o; o >>= 1) {
        s += __shfl_xor_sync(0xffffffffu, s, o);
        q += __shfl_xor_sync(0xffffffffu, q, o);
    }
    if (lane == 0) {
        const float mean = s * (1.f / 512.f);
        const float var  = q * (1.f / 512.f) - mean * mean;
        st[tok] = make_float2(mean, rsqrtf(var + 1e-12f));
    }
}

// ================= mma flash attention, TC expansion + fused O@V ============
template <int KV_TILES, bool TIME>
__global__ __launch_bounds__(128)
void attn_tc(const float* __restrict__ qlo, const float* __restrict__ klo,
             const float* __restrict__ vlow, const float* __restrict__ U,
             const float* __restrict__ Vw,
             const float* __restrict__ rc, const float* __restrict__ rs,
             float* __restrict__ olow, float* __restrict__ y)
{
    extern __shared__ float sm[];
    float* lot = sm + AT_LOT;
    float* ks  = sm + AT_KS;
    float* vs  = sm + AT_VS;

    const int tid  = threadIdx.x;
    const int lane = tid & 31;
    const int w    = tid >> 5;
    const int head = blockIdx.y;

    int base, step;
    if (TIME) {
        const int b = blockIdx.x >> 8;
        const int l = blockIdx.x & 255;
        base = b * (T_ * L_) + l;  step = L_;
    } else {
        base = blockIdx.x * L_;    step = 1;
    }
    const int q0 = blockIdx.z * 64;

    const int qr = lane >> 2;
    const int c  = lane & 3;

    uint32_t ub[8][2][2];
    #pragma unroll
    for (int j = 0; j < 8; ++j) {
        const float* up = U + ((size_t)head * 64 + j * 8 + qr) * 16 + 2 * c;
        float2 u0 = __ldg((const float2*)up);
        float2 u1 = __ldg((const float2*)(up + 8));
        ub[j][0][0] = f2tf(u0.x); ub[j][0][1] = f2tf(u0.y);
        ub[j][1][0] = f2tf(u1.x); ub[j][1][1] = f2tf(u1.y);
    }

    #pragma unroll
    for (int p = 0; p < 2; ++p) {
        const int idx = tid + p * 128;
        const int i = idx >> 2, r4 = (idx & 3) * 4;
        const int tok = base + (q0 + i) * step;
        *(float4*)&lot[i * LOP_ + r4] =
            *(const float4*)(qlo + (size_t)tok * RK_ + head * 16 + r4);
    }
    __syncthreads();

    uint32_t qa[8][4];
    {
        const float* a_s = lot + (w * 16 + qr) * LOP_ + 2 * c;
        float2 a00 = *(const float2*)(a_s);
        float2 a01 = *(const float2*)(a_s + 8 * LOP_);
        float2 a10 = *(const float2*)(a_s + 8);
        float2 a11 = *(const float2*)(a_s + 8 * LOP_ + 8);
        uint32_t af0[4] = { f2tf(a00.x), f2tf(a01.x), f2tf(a00.y), f2tf(a01.y) };
        uint32_t af1[4] = { f2tf(a10.x), f2tf(a11.x), f2tf(a10.y), f2tf(a11.y) };
        const int pos0 = q0 + w * 16 + qr;
        #pragma unroll
        for (int j = 0; j < 8; ++j) {
            float e[4] = {0.f, 0.f, 0.f, 0.f};
            mma_tf32(e, af0, ub[j][0]);
            mma_tf32(e, af1, ub[j][1]);
            const int ih = 4 * j + c;
            const float cs0 = __ldg(rc + pos0 * 32 + ih);
            const float sn0 = __ldg(rs + pos0 * 32 + ih);
            const float cs1 = __ldg(rc + (pos0 + 8) * 32 + ih);
            const float sn1 = __ldg(rs + (pos0 + 8) * 32 + ih);
            qa[j][0] = f2tf((e[0] * cs0 - e[1] * sn0) * 0.125f);
            qa[j][1] = f2tf((e[2] * cs1 - e[3] * sn1) * 0.125f);
            qa[j][2] = f2tf((e[0] * sn0 + e[1] * cs0) * 0.125f);
            qa[j][3] = f2tf((e[2] * sn1 + e[3] * cs1) * 0.125f);
        }
    }
    __syncthreads();

    float m0v = -1e30f, m1v = -1e30f, l0v = 0.f, l1v = 0.f;
    float accO[2][4];
    #pragma unroll
    for (int nf = 0; nf < 2; ++nf)
        #pragma unroll
        for (int r = 0; r < 4; ++r) accO[nf][r] = 0.f;

    for (int kt = 0; kt < KV_TILES; ++kt) {
        #pragma unroll
        for (int p = 0; p < 2; ++p) {
            const int idx = tid + p * 128;
            const int i = idx >> 2, r4 = (idx & 3) * 4;
            const int tok = base + (kt * 64 + i) * step;
            *(float4*)&lot[i * LOP_ + r4] =
                *(const float4*)(klo + (size_t)tok * RK_ + head * 16 + r4);
        }
        #pragma unroll
        for (int p = 0; p < 2; ++p) {
            const int f = tid + p * 128;
            const int j = f >> 2;
            const int rq = (f & 3) * 4;
            const int tok = base + (kt * 64 + j) * step;
            *(float4*)&vs[j * VP_ + rq] =
                *(const float4*)(vlow + (size_t)tok * RK_ + head * 16 + rq);
        }
        __syncthreads();

        {
            const float* a_s = lot + (w * 16 + qr) * LOP_ + 2 * c;
            float2 a00 = *(const float2*)(a_s);
            float2 a01 = *(const float2*)(a_s + 8 * LOP_);
            float2 a10 = *(const float2*)(a_s + 8);
            float2 a11 = *(const float2*)(a_s + 8 * LOP_ + 8);
            uint32_t af0[4] = { f2tf(a00.x), f2tf(a01.x), f2tf(a00.y), f2tf(a01.y) };
            uint32_t af1[4] = { f2tf(a10.x), f2tf(a11.x), f2tf(a10.y), f2tf(a11.y) };
            const int krow = w * 16 + qr;
            const int pos0 = kt * 64 + krow;
            #pragma unroll
            for (int j = 0; j < 8; ++j) {
                float e[4] = {0.f, 0.f, 0.f, 0.f};
                mma_tf32(e, af0, ub[j][0]);
                mma_tf32(e, af1, ub[j][1]);
                const int ih = 4 * j + c;
                const float cs0 = __ldg(rc + pos0 * 32 + ih);
                const float sn0 = __ldg(rs + pos0 * 32 + ih);
                const float cs1 = __ldg(rc + (pos0 + 8) * 32 + ih);
                const float sn1 = __ldg(rs + (pos0 + 8) * 32 + ih);
                *(float2*)&ks[krow * QKP_ + j * 8 + 2 * c] =
                    make_float2(e[0] * cs0 - e[1] * sn0,
                                e[0] * sn0 + e[1] * cs0);
                *(float2*)&ks[(krow + 8) * QKP_ + j * 8 + 2 * c] =
                    make_float2(e[2] * cs1 - e[3] * sn1,
                                e[2] * sn1 + e[3] * cs1);
            }
        }
        __syncthreads();

        float s[8][4];
        #pragma unroll
        for (int j = 0; j < 8; ++j)
            #pragma unroll
            for (int r = 0; r < 4; ++r) s[j][r] = 0.f;

        const float* b_s = ks + qr * QKP_ + 2 * c;
        #pragma unroll
        for (int ks8 = 0; ks8 < 8; ++ks8) {
            const int k0 = ks8 * 8;
            #pragma unroll
            for (int j = 0; j < 8; ++j) {
                float2 bb = *(const float2*)(b_s + j * 8 * QKP_ + k0);
                uint32_t bf[2] = { f2tf(bb.x), f2tf(bb.y) };
                mma_tf32(s[j], qa[ks8], bf);
            }
        }

        float tm0 = -1e30f, tm1 = -1e30f;
        #pragma unroll
        for (int j = 0; j < 8; ++j) {
            tm0 = fmaxf(tm0, fmaxf(s[j][0], s[j][1]));
            tm1 = fmaxf(tm1, fmaxf(s[j][2], s[j][3]));
        }
        tm0 = fmaxf(tm0, __shfl_xor_sync(0xffffffffu, tm0, 1));
        tm0 = fmaxf(tm0, __shfl_xor_sync(0xffffffffu, tm0, 2));
        tm1 = fmaxf(tm1, __shfl_xor_sync(0xffffffffu, tm1, 1));
        tm1 = fmaxf(tm1, __shfl_xor_sync(0xffffffffu, tm1, 2));

        const float mn0 = fmaxf(m0v, tm0);
        const float mn1 = fmaxf(m1v, tm1);
        const float al0 = __expf(m0v - mn0);
        const float al1 = __expf(m1v - mn1);
        m0v = mn0; m1v = mn1;

        float rs0 = 0.f, rs1 = 0.f;
        #pragma unroll
        for (int j = 0; j < 8; ++j) {
            s[j][0] = __expf(s[j][0] - mn0);
            s[j][1] = __expf(s[j][1] - mn0);
            s[j][2] = __expf(s[j][2] - mn1);
            s[j][3] = __expf(s[j][3] - mn1);
            rs0 += s[j][0] + s[j][1];
            rs1 += s[j][2] + s[j][3];
        }
        rs0 += __shfl_xor_sync(0xffffffffu, rs0, 1);
        rs0 += __shfl_xor_sync(0xffffffffu, rs0, 2);
        rs1 += __shfl_xor_sync(0xffffffffu, rs1, 1);
        rs1 += __shfl_xor_sync(0xffffffffu, rs1, 2);
        l0v = l0v * al0 + rs0;
        l1v = l1v * al1 + rs1;

        #pragma unroll
        for (int nf = 0; nf < 2; ++nf) {
            accO[nf][0] *= al0; accO[nf][1] *= al0;
            accO[nf][2] *= al1; accO[nf][3] *= al1;
        }

        #pragma unroll
        for (int j = 0; j < 8; ++j) {
            uint32_t pa[4];
            pa[0] = f2tf(s[j][0]);
            pa[1] = f2tf(s[j][2]);
            pa[2] = f2tf(s[j][1]);
            pa[3] = f2tf(s[j][3]);
            const float* vp = vs + (j * 8 + 2 * c) * VP_;
            #pragma unroll
            for (int nf = 0; nf < 2; ++nf) {
                const int col = nf * 8 + qr;
                uint32_t bf[2] = { f2tf(vp[col]), f2tf(vp[VP_ + col]) };
                mma_tf32(accO[nf], pa, bf);
            }
        }
        __syncthreads();
    }

    const float inv0 = 1.f / l0v;
    const float inv1 = 1.f / l1v;
    const int r0 = q0 + w * 16 + qr;
    const int r1 = r0 + 8;
    const size_t tok0 = (size_t)(base + r0 * step);
    const size_t tok1 = (size_t)(base + r1 * step);

    #pragma unroll
    for (int nf = 0; nf < 2; ++nf) {
        const int col = nf * 8 + c * 2;
        *(float2*)(olow + tok0 * RK_ + head * 16 + col) =
            make_float2(accO[nf][0] * inv0, accO[nf][1] * inv0);
        *(float2*)(olow + tok1 * RK_ + head * 16 + col) =
            make_float2(accO[nf][2] * inv1, accO[nf][3] * inv1);
    }

    uint32_t oa[2][4];
    #pragma unroll
    for (int s2 = 0; s2 < 2; ++s2) {
        oa[s2][0] = f2tf(accO[s2][0] * inv0);
        oa[s2][1] = f2tf(accO[s2][2] * inv1);
        oa[s2][2] = f2tf(accO[s2][1] * inv0);
        oa[s2][3] = f2tf(accO[s2][3] * inv1);
    }
    const float* Vh = Vw + (size_t)head * 1024;
    #pragma unroll
    for (int j = 0; j < 8; ++j) {
        float ya[4] = {0.f, 0.f, 0.f, 0.f};
        #pragma unroll
        for (int s2 = 0; s2 < 2; ++s2) {
            const int rr = s2 * 8 + 2 * c;
            uint32_t bf[2] = { f2tf(__ldg(Vh + rr * 64 + j * 8 + qr)),
                               f2tf(__ldg(Vh + (rr + 1) * 64 + j * 8 + qr)) };
            mma_tf32(ya, oa[s2], bf);
        }
        const int dcol = head * 64 + j * 8 + 2 * c;
        *(float2*)(y + tok0 * C_ + dcol) = make_float2(ya[0], ya[1]);
        *(float2*)(y + tok1 * C_ + dcol) = make_float2(ya[2], ya[3]);
    }
}

// ============================ launch ========================================
extern "C" void kernel_launch(void* const* d_in, const int* in_sizes, int n_in,
                              void* d_out, int out_size)
{
    const float* x    = (const float*)d_in[0];
    const float* tWq  = (const float*)d_in[3];
    const float* tWk  = (const float*)d_in[4];
    const float* tWv  = (const float*)d_in[5];
    const float* tU   = (const float*)d_in[6];
    const float* tV   = (const float*)d_in[7];
    const float* aWq  = (const float*)d_in[8];
    const float* aWk  = (const float*)d_in[9];
    const float* aWv  = (const float*)d_in[10];
    const float* aU   = (const float*)d_in[11];
    const float* aV   = (const float*)d_in[12];
    const float* ln1g = (const float*)d_in[13];
    const float* ln1b = (const float*)d_in[14];
    const float* ln2g = (const float*)d_in[15];
    const float* ln2b = (const float*)d_in[16];
    const float* ln3g = (const float*)d_in[17];
    const float* ln3b = (const float*)d_in[18];
    const float* projW= (const float*)d_in[19];
    const float* projb= (const float*)d_in[20];
    const float* gtW  = (const float*)d_in[21];
    const float* gtb  = (const float*)d_in[22];
    const float* gaW  = (const float*)d_in[23];
    const float* gab  = (const float*)d_in[24];
    float* out = (float*)d_out;

    float *yb, *x1, *x2, *qlo, *klo, *vlo, *olo;
    float *befft, *beffa, *ropec, *ropes;
    float2* stp;
    cudaGetSymbolAddress((void**)&yb,  g_y);
    cudaGetSymbolAddress((void**)&x1,  g_x1);
    cudaGetSymbolAddress((void**)&x2,  g_x2);
    cudaGetSymbolAddress((void**)&qlo, g_qlo);
    cudaGetSymbolAddress((void**)&klo, g_klo);
    cudaGetSymbolAddress((void**)&vlo, g_vlo);
    cudaGetSymbolAddress((void**)&olo, g_olo);
    cudaGetSymbolAddress((void**)&befft, g_befft);
    cudaGetSymbolAddress((void**)&beffa, g_beffa);
    cudaGetSymbolAddress((void**)&ropec, g_ropec);
    cudaGetSymbolAddress((void**)&ropes, g_ropes);
    cudaGetSymbolAddress((void**)&stp,  g_st);

    static bool attr_set = false;
    if (!attr_set) {
        cudaFuncSetAttribute(gemm_qkv, cudaFuncAttributeMaxDynamicSharedMemorySize, GEMM_SMEM);
        cudaFuncSetAttribute(gemm_gen<false>, cudaFuncAttributeMaxDynamicSharedMemorySize, GEMM_SMEM);
        cudaFuncSetAttribute(gemm_gen<true>,  cudaFuncAttributeMaxDynamicSharedMemorySize, GEMM_SMEM);
        cudaFuncSetAttribute(attn_tc<1, true>,  cudaFuncAttributeMaxDynamicSharedMemorySize, ATTN_SMEM);
        cudaFuncSetAttribute(attn_tc<4, false>, cudaFuncAttributeMaxDynamicSharedMemorySize, ATTN_SMEM);
        attr_set = true;
    }

    // -------- prep --------
    build_rope<<<32, 256>>>(ropec, ropes);
    build_beff<<<512, 128>>>(gtW, tV, befft);
    build_beff<<<512, 128>>>(gaW, aV, beffa);

    // ---------------- stage A: time attention ----------------
    ln_stats<<<N_ / 8, 256>>>(x, stp);
    gemm_qkv<<<3 * (N_ / 128), 256, GEMM_SMEM>>>(x, stp, ln1g, ln1b,
                                                 tWq, tWk, tWv, qlo, klo, vlo);
    attn_tc<1, true><<<dim3(B_ * L_, 8, 1), 128, ATTN_SMEM>>>(
        qlo, klo, vlo, tU, tV, ropec, ropes, olo, yb);
    gemm_gen<false><<<4 * (N_ / 128), 256, GEMM_SMEM>>>(
        x, 512, olo, 128, befft, gtb, x, yb, x1, 512, 640, 1,
        nullptr, nullptr, nullptr);

    // ---------------- stage B: residue attention ----------------
    ln_stats<<<N_ / 8, 256>>>(x1, stp);
    gemm_qkv<<<3 * (N_ / 128), 256, GEMM_SMEM>>>(x1, stp, ln2g, ln2b,
                                                 aWq, aWk, aWv, qlo, klo, vlo);
    attn_tc<4, false><<<dim3(B_ * T_, 8, 4), 128, ATTN_SMEM>>>(
        qlo, klo, vlo, aU, aV, ropec, ropes, olo, yb);
    gemm_gen<false><<<4 * (N_ / 128), 256, GEMM_SMEM>>>(
        x1, 512, olo, 128, beffa, gab, x1, yb, x2, 512, 640, 1,
        nullptr, nullptr, nullptr);

    // ---------------- stage C: output projection ----------------
    ln_stats<<<N_ / 8, 256>>>(x2, stp);
    gemm_gen<true><<<4 * (N_ / 128), 256, GEMM_SMEM>>>(
        x2, 512, x2, 512, projW, projb, x2, nullptr, out, 512, 512, 2,
        stp, ln3g, ln3b);
}

// round 13
// speedup vs baseline: 1.4939x; 1.0198x over previous
#include <cuda_runtime.h>
#include <cstdint>

// ============================================================================
// ProteinSpatioTemporalAttention — round 13:
//  - round-12 exposed: raw-bit tf32 feed = one-sided truncation => systematic
//    (1 - 2^-11) product shrink => rel_err 7.9e-4 (too close to 1e-3 gate).
//  - FIX: round-to-nearest via bit-add (bits + 0x1000) everywhere. Same
//    numerics as cvt.rna up to ties; IADD3 (lat 4) instead of CVT (lat ~20),
//    so the round-12 latency win is retained with round-11 precision.
// ============================================================================

namespace {
constexpr int B_  = 4;
constexpr int T_  = 64;
constexpr int L_  = 256;
constexpr int C_  = 512;
constexpr int RK_ = 128;
constexpr int N_  = B_ * T_ * L_;   // 65536 tokens

constexpr int PAD_ = 40;            // GEMM smem row stride (floats)
constexpr int GEMM_SMEM = 2 * 2 * 128 * PAD_ * 4;   // 81920 bytes

// attention smem layout (floats)
constexpr int LOP_ = 24;
constexpr int QKP_ = 72;
constexpr int VP_  = 20;
constexpr int AT_LOT = 0;                  // [64][24]
constexpr int AT_KS  = AT_LOT + 64 * LOP_; // [64][72]
constexpr int AT_VS  = AT_KS + 64 * QKP_;  // [64][20]
constexpr int AT_TOT = AT_VS + 64 * VP_;
constexpr int ATTN_SMEM = AT_TOT * 4;      // 29696 bytes
}

// -------------------- scratch (device globals; no cudaMalloc) ---------------
__device__ float  g_y  [N_ * C_];
__device__ float  g_x1 [N_ * C_];
__device__ float  g_x2 [N_ * C_];
__device__ float  g_qlo[N_ * RK_];
__device__ float  g_klo[N_ * RK_];
__device__ float  g_vlo[N_ * RK_];
__device__ float  g_olo[N_ * RK_];
__device__ float  g_befft[512 * 640];
__device__ float  g_beffa[512 * 640];
__device__ float  g_ropec[256 * 32];
__device__ float  g_ropes[256 * 32];
__device__ float2 g_st [N_];

// ============================ PTX helpers ===================================
__device__ __forceinline__ uint32_t smem_u32(const void* p) {
    uint32_t a;
    asm("{ .reg .u64 t; cvta.to.shared.u64 t, %1; cvt.u32.u64 %0, t; }"
        : "=r"(a) : "l"(p));
    return a;
}
// round-to-nearest tf32 via bit-add: HW mma truncates low 13 mantissa bits;
// adding half an ulp (0x1000) first gives round-to-nearest (ties up).
// One IADD3 (lat 4) vs cvt.rna (lat ~20) on the load->mma critical path.
__device__ __forceinline__ uint32_t f2tf(float x) {
    return __float_as_uint(x) + 0x1000u;
}
__device__ __forceinline__ void mma_tf32(float* c, const uint32_t* a, const uint32_t* b) {
    asm volatile("mma.sync.aligned.m16n8k8.row.col.f32.tf32.tf32.f32 "
        "{%0,%1,%2,%3}, {%4,%5,%6,%7}, {%8,%9}, {%0,%1,%2,%3};"
        : "+f"(c[0]), "+f"(c[1]), "+f"(c[2]), "+f"(c[3])
        : "r"(a[0]), "r"(a[1]), "r"(a[2]), "r"(a[3]), "r"(b[0]), "r"(b[1]));
}
#define CP_ASYNC16(dst, src) \
    asm volatile("cp.async.cg.shared.global [%0], [%1], 16;" :: "r"(dst), "l"(src))
#define CP_COMMIT() asm volatile("cp.async.commit_group;" ::: "memory")
#define CP_WAIT1()  asm volatile("cp.async.wait_group 1;" ::: "memory")
#define CP_WAIT0()  asm volatile("cp.async.wait_group 0;" ::: "memory")

// ============================ tf32 mma GEMM body ============================
template <bool LN>
__device__ __forceinline__
void gemm_body(const float* __restrict__ A0, int lda0,
               const float* __restrict__ A1, int lda1,
               const float* __restrict__ Bw,
               const float* __restrict__ bias,
               const float* __restrict__ resid,
               const float* __restrict__ yv,
               float* __restrict__ C, int ldc,
               int K1, int Kw, int mode, int m0, int n0,
               const float2* __restrict__ lnst,
               const float* __restrict__ lng,
               const float* __restrict__ lnb)
{
    extern __shared__ float sm[];
    float* As = sm;
    float* Bs = sm + 2 * 128 * PAD_;

    const int tid  = threadIdx.x;
    const int lane = tid & 31;
    const int wid  = tid >> 5;
    const int NC   = Kw >> 5;
    const int NC1  = K1 >> 5;

    const int lr = tid >> 3;
    const int lk = (tid & 7) * 4;

    const uint32_t aS0 = smem_u32(As);
    const uint32_t bS0 = smem_u32(Bs);

    auto prefetch = [&](int c, int s) {
        const float* Ap; int kb, lda;
        if (c < NC1) { Ap = A0; lda = lda0; kb = c * 32; }
        else         { Ap = A1; lda = lda1; kb = (c - NC1) * 32; }
        const uint32_t aT = aS0 + (uint32_t)(s * 128 * PAD_) * 4;
        const uint32_t bT = bS0 + (uint32_t)(s * 128 * PAD_) * 4;
        const float* srcB = Bw + (size_t)n0 * Kw + c * 32;
        #pragma unroll
        for (int it = 0; it < 4; ++it) {
            const int r = lr + it * 32;
            CP_ASYNC16(aT + (uint32_t)(r * PAD_ + lk) * 4,
                       Ap + (size_t)(m0 + r) * lda + kb + lk);
            CP_ASYNC16(bT + (uint32_t)(r * PAD_ + lk) * 4,
                       srcB + (size_t)r * Kw + lk);
        }
    };

    const int wm = (wid & 1) * 64;
    const int wn = (wid >> 1) * 32;
    const int qr = lane >> 2;
    const int tc = lane & 3;

    float2 st[4][2];
    if (LN) {
        #pragma unroll
        for (int i = 0; i < 4; ++i) {
            st[i][0] = __ldg(&lnst[m0 + wm + qr + i * 16]);
            st[i][1] = __ldg(&lnst[m0 + wm + qr + i * 16 + 8]);
        }
    }

    float acc[4][4][4];
    #pragma unroll
    for (int i = 0; i < 4; ++i)
        #pragma unroll
        for (int j = 0; j < 4; ++j)
            #pragma unroll
            for (int r = 0; r < 4; ++r) acc[i][j][r] = 0.f;

    prefetch(0, 0);
    CP_COMMIT();

    for (int ch = 0; ch < NC; ++ch) {
        const int s = ch & 1;
        if (ch + 1 < NC) { prefetch(ch + 1, s ^ 1); CP_COMMIT(); CP_WAIT1(); }
        else             { CP_WAIT0(); }
        __syncthreads();

        const float* a_s = As + s * 128 * PAD_ + (wm + qr) * PAD_ + 2 * tc;
        const float* b_s = Bs + s * 128 * PAD_ + (wn + qr) * PAD_ + 2 * tc;

        #pragma unroll
        for (int ks = 0; ks < 4; ++ks) {
            const int k0 = ks * 8;
            float2 g2, b2;
            if (LN) {
                const int kcol = ch * 32 + k0 + 2 * tc;
                g2 = __ldg((const float2*)(lng + kcol));
                b2 = __ldg((const float2*)(lnb + kcol));
            }
            uint32_t af[4][4];
            #pragma unroll
            for (int i = 0; i < 4; ++i) {
                float2 a0 = *(const float2*)(a_s + i * 16 * PAD_ + k0);
                float2 a1 = *(const float2*)(a_s + i * 16 * PAD_ + 8 * PAD_ + k0);
                if (LN) {
                    a0.x = (a0.x - st[i][0].x) * st[i][0].y * g2.x + b2.x;
                    a0.y = (a0.y - st[i][0].x) * st[i][0].y * g2.y + b2.y;
                    a1.x = (a1.x - st[i][1].x) * st[i][1].y * g2.x + b2.x;
                    a1.y = (a1.y - st[i][1].x) * st[i][1].y * g2.y + b2.y;
                }
                af[i][0] = f2tf(a0.x);
                af[i][1] = f2tf(a1.x);
                af[i][2] = f2tf(a0.y);
                af[i][3] = f2tf(a1.y);
            }
            #pragma unroll
            for (int j = 0; j < 4; ++j) {
                float2 bb = *(const float2*)(b_s + j * 8 * PAD_ + k0);
                uint32_t bf[2] = { f2tf(bb.x), f2tf(bb.y) };
                #pragma unroll
                for (int i = 0; i < 4; ++i) mma_tf32(acc[i][j], af[i], bf);
            }
        }
        __syncthreads();
    }

    const int row0 = m0 + wm + qr;
    const int col0 = n0 + wn + tc * 2;

    #pragma unroll
    for (int i = 0; i < 4; ++i) {
        #pragma unroll
        for (int half = 0; half < 2; ++half) {
            const int r = row0 + i * 16 + half * 8;
            float*       crow = C + (size_t)r * ldc;
            const float* rrow = resid ? resid + (size_t)r * ldc : nullptr;
            const float* yrow = yv    ? yv    + (size_t)r * ldc : nullptr;
            #pragma unroll
            for (int j = 0; j < 4; ++j) {
                const int cc = col0 + j * 8;
                float v0 = acc[i][j][half * 2 + 0];
                float v1 = acc[i][j][half * 2 + 1];
                if (mode == 0) {
                    *(float2*)(crow + cc) = make_float2(v0, v1);
                } else if (mode == 1) {
                    float2 bi = *(const float2*)(bias + cc);
                    float2 rv = *(const float2*)(rrow + cc);
                    float2 yw = *(const float2*)(yrow + cc);
                    float g0 = 1.f / (1.f + __expf(-(v0 + bi.x)));
                    float g1 = 1.f / (1.f + __expf(-(v1 + bi.y)));
                    *(float2*)(crow + cc) = make_float2(
                        g0 * rv.x + (1.f - g0) * yw.x,
                        g1 * rv.y + (1.f - g1) * yw.y);
                } else {
                    float2 bi = *(const float2*)(bias + cc);
                    float2 rv = *(const float2*)(rrow + cc);
                    *(float2*)(crow + cc) = make_float2(v0 + bi.x + rv.x,
                                                        v1 + bi.y + rv.y);
                }
            }
        }
    }
}

// QKV with fused LN on A.
__global__ __launch_bounds__(256, 2)
void gemm_qkv(const float* __restrict__ A,
              const float2* __restrict__ lnst,
              const float* __restrict__ lng, const float* __restrict__ lnb,
              const float* __restrict__ Wq, const float* __restrict__ Wk,
              const float* __restrict__ Wv,
              float* __restrict__ q, float* __restrict__ k, float* __restrict__ v)
{
    const int bx  = blockIdx.x;
    const int sel = bx % 3;
    const int m0  = (bx / 3) * 128;
    const float* Bw = (sel == 0) ? Wq : (sel == 1) ? Wk : Wv;
    float*       C  = (sel == 0) ? q  : (sel == 1) ? k  : v;
    gemm_body<true>(A, 512, A, 512, Bw, nullptr, nullptr, nullptr, C, 128,
                    512, 512, 0, m0, 0, lnst, lng, lnb);
}

template <bool LN>
__global__ __launch_bounds__(256, 2)
void gemm_gen(const float* __restrict__ A0, int lda0,
              const float* __restrict__ A1, int lda1,
              const float* __restrict__ Bw,
              const float* __restrict__ bias,
              const float* __restrict__ resid,
              const float* __restrict__ yv,
              float* __restrict__ C, int K1, int Kw, int mode,
              const float2* __restrict__ lnst,
              const float* __restrict__ lng, const float* __restrict__ lnb)
{
    const int bx = blockIdx.x;
    const int m0 = (bx >> 2) * 128;
    const int n0 = (bx & 3) * 128;
    gemm_body<LN>(A0, lda0, A1, lda1, Bw, bias, resid, yv, C, 512,
                  K1, Kw, mode, m0, n0, lnst, lng, lnb);
}

// ============================ prep kernels ==================================
__global__ void build_beff(const float* __restrict__ gW,
                           const float* __restrict__ V,
                           float* __restrict__ Beff)
{
    const int n = blockIdx.x;
    const int tid = threadIdx.x;
    ((float4*)(Beff + (size_t)n * 640))[tid] =
        ((const float4*)(gW + (size_t)n * 1024))[tid];
    const int h = tid >> 4, r = tid & 15;
    const float* w2 = gW + (size_t)n * 1024 + 512 + h * 64;
    const float* vr = V + (size_t)(h * 16 + r) * 64;
    float s = 0.f;
    #pragma unroll
    for (int d = 0; d < 64; ++d) s = fmaf(w2[d], vr[d], s);
    Beff[(size_t)n * 640 + 512 + tid] = s;
}

__global__ void build_rope(float* __restrict__ rc, float* __restrict__ rs)
{
    const int idx = blockIdx.x * 256 + threadIdx.x;
    const int pos = idx >> 5;
    const int ih  = idx & 31;
    const float theta = expf((float)ih * -0.28782313662425572f);
    float sn, cs;
    sincosf((float)pos * theta, &sn, &cs);
    rc[idx] = cs;  rs[idx] = sn;
}

// ===================== LN stats (mean, rstd per token) ======================
__global__ void ln_stats(const float* __restrict__ x, float2* __restrict__ st)
{
    const int tok  = blockIdx.x * 8 + (threadIdx.x >> 5);
    const int lane = threadIdx.x & 31;
    const float4* xr = (const float4*)(x + (size_t)tok * C_);
    float s = 0.f, q = 0.f;
    #pragma unroll
    for (int p = 0; p < 4; ++p) {
        float4 v = xr[lane + p * 32];
        s += v.x + v.y + v.z + v.w;
        q += v.x * v.x + v.y * v.y + v.z * v.z + v.w * v.w;
    }
    #pragma unroll
    for (int o = 16; o; o >>= 1) {
        s += __shfl_xor_sync(0xffffffffu, s, o);
        q += __shfl_xor_sync(0xffffffffu, q, o);
    }
    if (lane == 0) {
        const float mean = s * (1.f / 512.f);
        const float var  = q * (1.f / 512.f) - mean * mean;
        st[tok] = make_float2(mean, rsqrtf(var + 1e-12f));
    }
}

// ================= mma flash attention, TC expansion + fused O@V ============
template <int KV_TILES, bool TIME>
__global__ __launch_bounds__(128)
void attn_tc(const float* __restrict__ qlo, const float* __restrict__ klo,
             const float* __restrict__ vlow, const float* __restrict__ U,
             const float* __restrict__ Vw,
             const float* __restrict__ rc, const float* __restrict__ rs,
             float* __restrict__ olow, float* __restrict__ y)
{
    extern __shared__ float sm[];
    float* lot = sm + AT_LOT;
    float* ks  = sm + AT_KS;
    float* vs  = sm + AT_VS;

    const int tid  = threadIdx.x;
    const int lane = tid & 31;
    const int w    = tid >> 5;
    const int head = blockIdx.y;

    int base, step;
    if (TIME) {
        const int b = blockIdx.x >> 8;
        const int l = blockIdx.x & 255;
        base = b * (T_ * L_) + l;  step = L_;
    } else {
        base = blockIdx.x * L_;    step = 1;
    }
    const int q0 = blockIdx.z * 64;

    const int qr = lane >> 2;
    const int c  = lane & 3;

    uint32_t ub[8][2][2];
    #pragma unroll
    for (int j = 0; j < 8; ++j) {
        const float* up = U + ((size_t)head * 64 + j * 8 + qr) * 16 + 2 * c;
        float2 u0 = __ldg((const float2*)up);
        float2 u1 = __ldg((const float2*)(up + 8));
        ub[j][0][0] = f2tf(u0.x); ub[j][0][1] = f2tf(u0.y);
        ub[j][1][0] = f2tf(u1.x); ub[j][1][1] = f2tf(u1.y);
    }

    #pragma unroll
    for (int p = 0; p < 2; ++p) {
        const int idx = tid + p * 128;
        const int i = idx >> 2, r4 = (idx & 3) * 4;
        const int tok = base + (q0 + i) * step;
        *(float4*)&lot[i * LOP_ + r4] =
            *(const float4*)(qlo + (size_t)tok * RK_ + head * 16 + r4);
    }
    __syncthreads();

    uint32_t qa[8][4];
    {
        const float* a_s = lot + (w * 16 + qr) * LOP_ + 2 * c;
        float2 a00 = *(const float2*)(a_s);
        float2 a01 = *(const float2*)(a_s + 8 * LOP_);
        float2 a10 = *(const float2*)(a_s + 8);
        float2 a11 = *(const float2*)(a_s + 8 * LOP_ + 8);
        uint32_t af0[4] = { f2tf(a00.x), f2tf(a01.x), f2tf(a00.y), f2tf(a01.y) };
        uint32_t af1[4] = { f2tf(a10.x), f2tf(a11.x), f2tf(a10.y), f2tf(a11.y) };
        const int pos0 = q0 + w * 16 + qr;
        #pragma unroll
        for (int j = 0; j < 8; ++j) {
            float e[4] = {0.f, 0.f, 0.f, 0.f};
            mma_tf32(e, af0, ub[j][0]);
            mma_tf32(e, af1, ub[j][1]);
            const int ih = 4 * j + c;
            const float cs0 = __ldg(rc + pos0 * 32 + ih);
            const float sn0 = __ldg(rs + pos0 * 32 + ih);
            const float cs1 = __ldg(rc + (pos0 + 8) * 32 + ih);
            const float sn1 = __ldg(rs + (pos0 + 8) * 32 + ih);
            qa[j][0] = f2tf((e[0] * cs0 - e[1] * sn0) * 0.125f);
            qa[j][1] = f2tf((e[2] * cs1 - e[3] * sn1) * 0.125f);
            qa[j][2] = f2tf((e[0] * sn0 + e[1] * cs0) * 0.125f);
            qa[j][3] = f2tf((e[2] * sn1 + e[3] * cs1) * 0.125f);
        }
    }
    __syncthreads();

    float m0v = -1e30f, m1v = -1e30f, l0v = 0.f, l1v = 0.f;
    float accO[2][4];
    #pragma unroll
    for (int nf = 0; nf < 2; ++nf)
        #pragma unroll
        for (int r = 0; r < 4; ++r) accO[nf][r] = 0.f;

    for (int kt = 0; kt < KV_TILES; ++kt) {
        #pragma unroll
        for (int p = 0; p < 2; ++p) {
            const int idx = tid + p * 128;
            const int i = idx >> 2, r4 = (idx & 3) * 4;
            const int tok = base + (kt * 64 + i) * step;
            *(float4*)&lot[i * LOP_ + r4] =
                *(const float4*)(klo + (size_t)tok * RK_ + head * 16 + r4);
        }
        #pragma unroll
        for (int p = 0; p < 2; ++p) {
            const int f = tid + p * 128;
            const int j = f >> 2;
            const int rq = (f & 3) * 4;
            const int tok = base + (kt * 64 + j) * step;
            *(float4*)&vs[j * VP_ + rq] =
                *(const float4*)(vlow + (size_t)tok * RK_ + head * 16 + rq);
        }
        __syncthreads();

        {
            const float* a_s = lot + (w * 16 + qr) * LOP_ + 2 * c;
            float2 a00 = *(const float2*)(a_s);
            float2 a01 = *(const float2*)(a_s + 8 * LOP_);
            float2 a10 = *(const float2*)(a_s + 8);
            float2 a11 = *(const float2*)(a_s + 8 * LOP_ + 8);
            uint32_t af0[4] = { f2tf(a00.x), f2tf(a01.x), f2tf(a00.y), f2tf(a01.y) };
            uint32_t af1[4] = { f2tf(a10.x), f2tf(a11.x), f2tf(a10.y), f2tf(a11.y) };
            const int krow = w * 16 + qr;
            const int pos0 = kt * 64 + krow;
            #pragma unroll
            for (int j = 0; j < 8; ++j) {
                float e[4] = {0.f, 0.f, 0.f, 0.f};
                mma_tf32(e, af0, ub[j][0]);
                mma_tf32(e, af1, ub[j][1]);
                const int ih = 4 * j + c;
                const float cs0 = __ldg(rc + pos0 * 32 + ih);
                const float sn0 = __ldg(rs + pos0 * 32 + ih);
                const float cs1 = __ldg(rc + (pos0 + 8) * 32 + ih);
                const float sn1 = __ldg(rs + (pos0 + 8) * 32 + ih);
                *(float2*)&ks[krow * QKP_ + j * 8 + 2 * c] =
                    make_float2(e[0] * cs0 - e[1] * sn0,
                                e[0] * sn0 + e[1] * cs0);
                *(float2*)&ks[(krow + 8) * QKP_ + j * 8 + 2 * c] =
                    make_float2(e[2] * cs1 - e[3] * sn1,
                                e[2] * sn1 + e[3] * cs1);
            }
        }
        __syncthreads();

        float s[8][4];
        #pragma unroll
        for (int j = 0; j < 8; ++j)
            #pragma unroll
            for (int r = 0; r < 4; ++r) s[j][r] = 0.f;

        const float* b_s = ks + qr * QKP_ + 2 * c;
        #pragma unroll
        for (int ks8 = 0; ks8 < 8; ++ks8) {
            const int k0 = ks8 * 8;
            #pragma unroll
            for (int j = 0; j < 8; ++j) {
                float2 bb = *(const float2*)(b_s + j * 8 * QKP_ + k0);
                uint32_t bf[2] = { f2tf(bb.x), f2tf(bb.y) };
                mma_tf32(s[j], qa[ks8], bf);
            }
        }

        float tm0 = -1e30f, tm1 = -1e30f;
        #pragma unroll
        for (int j = 0; j < 8; ++j) {
            tm0 = fmaxf(tm0, fmaxf(s[j][0], s[j][1]));
            tm1 = fmaxf(tm1, fmaxf(s[j][2], s[j][3]));
        }
        tm0 = fmaxf(tm0, __shfl_xor_sync(0xffffffffu, tm0, 1));
        tm0 = fmaxf(tm0, __shfl_xor_sync(0xffffffffu, tm0, 2));
        tm1 = fmaxf(tm1, __shfl_xor_sync(0xffffffffu, tm1, 1));
        tm1 = fmaxf(tm1, __shfl_xor_sync(0xffffffffu, tm1, 2));

        const float mn0 = fmaxf(m0v, tm0);
        const float mn1 = fmaxf(m1v, tm1);
        const float al0 = __expf(m0v - mn0);
        const float al1 = __expf(m1v - mn1);
        m0v = mn0; m1v = mn1;

        float rs0 = 0.f, rs1 = 0.f;
        #pragma unroll
        for (int j = 0; j < 8; ++j) {
            s[j][0] = __expf(s[j][0] - mn0);
            s[j][1] = __expf(s[j][1] - mn0);
            s[j][2] = __expf(s[j][2] - mn1);
            s[j][3] = __expf(s[j][3] - mn1);
            rs0 += s[j][0] + s[j][1];
            rs1 += s[j][2] + s[j][3];
        }
        rs0 += __shfl_xor_sync(0xffffffffu, rs0, 1);
        rs0 += __shfl_xor_sync(0xffffffffu, rs0, 2);
        rs1 += __shfl_xor_sync(0xffffffffu, rs1, 1);
        rs1 += __shfl_xor_sync(0xffffffffu, rs1, 2);
        l0v = l0v * al0 + rs0;
        l1v = l1v * al1 + rs1;

        #pragma unroll
        for (int nf = 0; nf < 2; ++nf) {
            accO[nf][0] *= al0; accO[nf][1] *= al0;
            accO[nf][2] *= al1; accO[nf][3] *= al1;
        }

        #pragma unroll
        for (int j = 0; j < 8; ++j) {
            uint32_t pa[4];
            pa[0] = f2tf(s[j][0]);
            pa[1] = f2tf(s[j][2]);
            pa[2] = f2tf(s[j][1]);
            pa[3] = f2tf(s[j][3]);
            const float* vp = vs + (j * 8 + 2 * c) * VP_;
            #pragma unroll
            for (int nf = 0; nf < 2; ++nf) {
                const int col = nf * 8 + qr;
                uint32_t bf[2] = { f2tf(vp[col]), f2tf(vp[VP_ + col]) };
                mma_tf32(accO[nf], pa, bf);
            }
        }
        __syncthreads();
    }

    const float inv0 = 1.f / l0v;
    const float inv1 = 1.f / l1v;
    const int r0 = q0 + w * 16 + qr;
    const int r1 = r0 + 8;
    const size_t tok0 = (size_t)(base + r0 * step);
    const size_t tok1 = (size_t)(base + r1 * step);

    #pragma unroll
    for (int nf = 0; nf < 2; ++nf) {
        const int col = nf * 8 + c * 2;
        *(float2*)(olow + tok0 * RK_ + head * 16 + col) =
            make_float2(accO[nf][0] * inv0, accO[nf][1] * inv0);
        *(float2*)(olow + tok1 * RK_ + head * 16 + col) =
            make_float2(accO[nf][2] * inv1, accO[nf][3] * inv1);
    }

    uint32_t oa[2][4];
    #pragma unroll
    for (int s2 = 0; s2 < 2; ++s2) {
        oa[s2][0] = f2tf(accO[s2][0] * inv0);
        oa[s2][1] = f2tf(accO[s2][2] * inv1);
        oa[s2][2] = f2tf(accO[s2][1] * inv0);
        oa[s2][3] = f2tf(accO[s2][3] * inv1);
    }
    const float* Vh = Vw + (size_t)head * 1024;
    #pragma unroll
    for (int j = 0; j < 8; ++j) {
        float ya[4] = {0.f, 0.f, 0.f, 0.f};
        #pragma unroll
        for (int s2 = 0; s2 < 2; ++s2) {
            const int rr = s2 * 8 + 2 * c;
            uint32_t bf[2] = { f2tf(__ldg(Vh + rr * 64 + j * 8 + qr)),
                               f2tf(__ldg(Vh + (rr + 1) * 64 + j * 8 + qr)) };
            mma_tf32(ya, oa[s2], bf);
        }
        const int dcol = head * 64 + j * 8 + 2 * c;
        *(float2*)(y + tok0 * C_ + dcol) = make_float2(ya[0], ya[1]);
        *(float2*)(y + tok1 * C_ + dcol) = make_float2(ya[2], ya[3]);
    }
}

// ============================ launch ========================================
extern "C" void kernel_launch(void* const* d_in, const int* in_sizes, int n_in,
                              void* d_out, int out_size)
{
    const float* x    = (const float*)d_in[0];
    const float* tWq  = (const float*)d_in[3];
    const float* tWk  = (const float*)d_in[4];
    const float* tWv  = (const float*)d_in[5];
    const float* tU   = (const float*)d_in[6];
    const float* tV   = (const float*)d_in[7];
    const float* aWq  = (const float*)d_in[8];
    const float* aWk  = (const float*)d_in[9];
    const float* aWv  = (const float*)d_in[10];
    const float* aU   = (const float*)d_in[11];
    const float* aV   = (const float*)d_in[12];
    const float* ln1g = (const float*)d_in[13];
    const float* ln1b = (const float*)d_in[14];
    const float* ln2g = (const float*)d_in[15];
    const float* ln2b = (const float*)d_in[16];
    const float* ln3g = (const float*)d_in[17];
    const float* ln3b = (const float*)d_in[18];
    const float* projW= (const float*)d_in[19];
    const float* projb= (const float*)d_in[20];
    const float* gtW  = (const float*)d_in[21];
    const float* gtb  = (const float*)d_in[22];
    const float* gaW  = (const float*)d_in[23];
    const float* gab  = (const float*)d_in[24];
    float* out = (float*)d_out;

    float *yb, *x1, *x2, *qlo, *klo, *vlo, *olo;
    float *befft, *beffa, *ropec, *ropes;
    float2* stp;
    cudaGetSymbolAddress((void**)&yb,  g_y);
    cudaGetSymbolAddress((void**)&x1,  g_x1);
    cudaGetSymbolAddress((void**)&x2,  g_x2);
    cudaGetSymbolAddress((void**)&qlo, g_qlo);
    cudaGetSymbolAddress((void**)&klo, g_klo);
    cudaGetSymbolAddress((void**)&vlo, g_vlo);
    cudaGetSymbolAddress((void**)&olo, g_olo);
    cudaGetSymbolAddress((void**)&befft, g_befft);
    cudaGetSymbolAddress((void**)&beffa, g_beffa);
    cudaGetSymbolAddress((void**)&ropec, g_ropec);
    cudaGetSymbolAddress((void**)&ropes, g_ropes);
    cudaGetSymbolAddress((void**)&stp,  g_st);

    static bool attr_set = false;
    if (!attr_set) {
        cudaFuncSetAttribute(gemm_qkv, cudaFuncAttributeMaxDynamicSharedMemorySize, GEMM_SMEM);
        cudaFuncSetAttribute(gemm_gen<false>, cudaFuncAttributeMaxDynamicSharedMemorySize, GEMM_SMEM);
        cudaFuncSetAttribute(gemm_gen<true>,  cudaFuncAttributeMaxDynamicSharedMemorySize, GEMM_SMEM);
        cudaFuncSetAttribute(attn_tc<1, true>,  cudaFuncAttributeMaxDynamicSharedMemorySize, ATTN_SMEM);
        cudaFuncSetAttribute(attn_tc<4, false>, cudaFuncAttributeMaxDynamicSharedMemorySize, ATTN_SMEM);
        attr_set = true;
    }

    // -------- prep --------
    build_rope<<<32, 256>>>(ropec, ropes);
    build_beff<<<512, 128>>>(gtW, tV, befft);
    build_beff<<<512, 128>>>(gaW, aV, beffa);

    // ---------------- stage A: time attention ----------------
    ln_stats<<<N_ / 8, 256>>>(x, stp);
    gemm_qkv<<<3 * (N_ / 128), 256, GEMM_SMEM>>>(x, stp, ln1g, ln1b,
                                                 tWq, tWk, tWv, qlo, klo, vlo);
    attn_tc<1, true><<<dim3(B_ * L_, 8, 1), 128, ATTN_SMEM>>>(
        qlo, klo, vlo, tU, tV, ropec, ropes, olo, yb);
    gemm_gen<false><<<4 * (N_ / 128), 256, GEMM_SMEM>>>(
        x, 512, olo, 128, befft, gtb, x, yb, x1, 512, 640, 1,
        nullptr, nullptr, nullptr);

    // ---------------- stage B: residue attention ----------------
    ln_stats<<<N_ / 8, 256>>>(x1, stp);
    gemm_qkv<<<3 * (N_ / 128), 256, GEMM_SMEM>>>(x1, stp, ln2g, ln2b,
                                                 aWq, aWk, aWv, qlo, klo, vlo);
    attn_tc<4, false><<<dim3(B_ * T_, 8, 4), 128, ATTN_SMEM>>>(
        qlo, klo, vlo, aU, aV, ropec, ropes, olo, yb);
    gemm_gen<false><<<4 * (N_ / 128), 256, GEMM_SMEM>>>(
        x1, 512, olo, 128, beffa, gab, x1, yb, x2, 512, 640, 1,
        nullptr, nullptr, nullptr);

    // ---------------- stage C: output projection ----------------
    ln_stats<<<N_ / 8, 256>>>(x2, stp);
    gemm_gen<true><<<4 * (N_ / 128), 256, GEMM_SMEM>>>(
        x2, 512, x2, 512, projW, projb, x2, nullptr, out, 512, 512, 2,
        stp, ln3g, ln3b);
}

// round 14
// speedup vs baseline: 1.5872x; 1.0625x over previous
#include <cuda_runtime.h>
#include <cstdint>

// ============================================================================
// ProteinSpatioTemporalAttention — round 14:
//  - aa-stage attention uses QT=2 (128-row q-tile per block): K expansion,
//    klo and V tile loads per (seq,head) drop from 4x to 2x redundancy.
//    Time stage stays QT=1. Identical math order => identical rel_err.
//  - round-13 bit-add tf32 rounding and all other structure unchanged.
// ============================================================================

namespace {
constexpr int B_  = 4;
constexpr int T_  = 64;
constexpr int L_  = 256;
constexpr int C_  = 512;
constexpr int RK_ = 128;
constexpr int N_  = B_ * T_ * L_;   // 65536 tokens

constexpr int PAD_ = 40;            // GEMM smem row stride (floats)
constexpr int GEMM_SMEM = 2 * 2 * 128 * PAD_ * 4;   // 81920 bytes

// attention smem layout (floats)
constexpr int LOP_ = 24;
constexpr int QKP_ = 72;
constexpr int VP_  = 20;
constexpr int AT_LOT = 0;                  // [64][24]
constexpr int AT_KS  = AT_LOT + 64 * LOP_; // [64][72]
constexpr int AT_VS  = AT_KS + 64 * QKP_;  // [64][20]
constexpr int AT_TOT = AT_VS + 64 * VP_;
constexpr int ATTN_SMEM = AT_TOT * 4;      // 29696 bytes
}

// -------------------- scratch (device globals; no cudaMalloc) ---------------
__device__ float  g_y  [N_ * C_];
__device__ float  g_x1 [N_ * C_];
__device__ float  g_x2 [N_ * C_];
__device__ float  g_qlo[N_ * RK_];
__device__ float  g_klo[N_ * RK_];
__device__ float  g_vlo[N_ * RK_];
__device__ float  g_olo[N_ * RK_];
__device__ float  g_befft[512 * 640];
__device__ float  g_beffa[512 * 640];
__device__ float  g_ropec[256 * 32];
__device__ float  g_ropes[256 * 32];
__device__ float2 g_st [N_];

// ============================ PTX helpers ===================================
__device__ __forceinline__ uint32_t smem_u32(const void* p) {
    uint32_t a;
    asm("{ .reg .u64 t; cvta.to.shared.u64 t, %1; cvt.u32.u64 %0, t; }"
        : "=r"(a) : "l"(p));
    return a;
}
// round-to-nearest tf32 via bit-add (HW mma truncates low 13 bits).
__device__ __forceinline__ uint32_t f2tf(float x) {
    return __float_as_uint(x) + 0x1000u;
}
__device__ __forceinline__ void mma_tf32(float* c, const uint32_t* a, const uint32_t* b) {
    asm volatile("mma.sync.aligned.m16n8k8.row.col.f32.tf32.tf32.f32 "
        "{%0,%1,%2,%3}, {%4,%5,%6,%7}, {%8,%9}, {%0,%1,%2,%3};"
        : "+f"(c[0]), "+f"(c[1]), "+f"(c[2]), "+f"(c[3])
        : "r"(a[0]), "r"(a[1]), "r"(a[2]), "r"(a[3]), "r"(b[0]), "r"(b[1]));
}
#define CP_ASYNC16(dst, src) \
    asm volatile("cp.async.cg.shared.global [%0], [%1], 16;" :: "r"(dst), "l"(src))
#define CP_COMMIT() asm volatile("cp.async.commit_group;" ::: "memory")
#define CP_WAIT1()  asm volatile("cp.async.wait_group 1;" ::: "memory")
#define CP_WAIT0()  asm volatile("cp.async.wait_group 0;" ::: "memory")

// ============================ tf32 mma GEMM body ============================
template <bool LN>
__device__ __forceinline__
void gemm_body(const float* __restrict__ A0, int lda0,
               const float* __restrict__ A1, int lda1,
               const float* __restrict__ Bw,
               const float* __restrict__ bias,
               const float* __restrict__ resid,
               const float* __restrict__ yv,
               float* __restrict__ C, int ldc,
               int K1, int Kw, int mode, int m0, int n0,
               const float2* __restrict__ lnst,
               const float* __restrict__ lng,
               const float* __restrict__ lnb)
{
    extern __shared__ float sm[];
    float* As = sm;
    float* Bs = sm + 2 * 128 * PAD_;

    const int tid  = threadIdx.x;
    const int lane = tid & 31;
    const int wid  = tid >> 5;
    const int NC   = Kw >> 5;
    const int NC1  = K1 >> 5;

    const int lr = tid >> 3;
    const int lk = (tid & 7) * 4;

    const uint32_t aS0 = smem_u32(As);
    const uint32_t bS0 = smem_u32(Bs);

    auto prefetch = [&](int c, int s) {
        const float* Ap; int kb, lda;
        if (c < NC1) { Ap = A0; lda = lda0; kb = c * 32; }
        else         { Ap = A1; lda = lda1; kb = (c - NC1) * 32; }
        const uint32_t aT = aS0 + (uint32_t)(s * 128 * PAD_) * 4;
        const uint32_t bT = bS0 + (uint32_t)(s * 128 * PAD_) * 4;
        const float* srcB = Bw + (size_t)n0 * Kw + c * 32;
        #pragma unroll
        for (int it = 0; it < 4; ++it) {
            const int r = lr + it * 32;
            CP_ASYNC16(aT + (uint32_t)(r * PAD_ + lk) * 4,
                       Ap + (size_t)(m0 + r) * lda + kb + lk);
            CP_ASYNC16(bT + (uint32_t)(r * PAD_ + lk) * 4,
                       srcB + (size_t)r * Kw + lk);
        }
    };

    const int wm = (wid & 1) * 64;
    const int wn = (wid >> 1) * 32;
    const int qr = lane >> 2;
    const int tc = lane & 3;

    float2 st[4][2];
    if (LN) {
        #pragma unroll
        for (int i = 0; i < 4; ++i) {
            st[i][0] = __ldg(&lnst[m0 + wm + qr + i * 16]);
            st[i][1] = __ldg(&lnst[m0 + wm + qr + i * 16 + 8]);
        }
    }

    float acc[4][4][4];
    #pragma unroll
    for (int i = 0; i < 4; ++i)
        #pragma unroll
        for (int j = 0; j < 4; ++j)
            #pragma unroll
            for (int r = 0; r < 4; ++r) acc[i][j][r] = 0.f;

    prefetch(0, 0);
    CP_COMMIT();

    for (int ch = 0; ch < NC; ++ch) {
        const int s = ch & 1;
        if (ch + 1 < NC) { prefetch(ch + 1, s ^ 1); CP_COMMIT(); CP_WAIT1(); }
        else             { CP_WAIT0(); }
        __syncthreads();

        const float* a_s = As + s * 128 * PAD_ + (wm + qr) * PAD_ + 2 * tc;
        const float* b_s = Bs + s * 128 * PAD_ + (wn + qr) * PAD_ + 2 * tc;

        #pragma unroll
        for (int ks = 0; ks < 4; ++ks) {
            const int k0 = ks * 8;
            float2 g2, b2;
            if (LN) {
                const int kcol = ch * 32 + k0 + 2 * tc;
                g2 = __ldg((const float2*)(lng + kcol));
                b2 = __ldg((const float2*)(lnb + kcol));
            }
            uint32_t af[4][4];
            #pragma unroll
            for (int i = 0; i < 4; ++i) {
                float2 a0 = *(const float2*)(a_s + i * 16 * PAD_ + k0);
                float2 a1 = *(const float2*)(a_s + i * 16 * PAD_ + 8 * PAD_ + k0);
                if (LN) {
                    a0.x = (a0.x - st[i][0].x) * st[i][0].y * g2.x + b2.x;
                    a0.y = (a0.y - st[i][0].x) * st[i][0].y * g2.y + b2.y;
                    a1.x = (a1.x - st[i][1].x) * st[i][1].y * g2.x + b2.x;
                    a1.y = (a1.y - st[i][1].x) * st[i][1].y * g2.y + b2.y;
                }
                af[i][0] = f2tf(a0.x);
                af[i][1] = f2tf(a1.x);
                af[i][2] = f2tf(a0.y);
                af[i][3] = f2tf(a1.y);
            }
            #pragma unroll
            for (int j = 0; j < 4; ++j) {
                float2 bb = *(const float2*)(b_s + j * 8 * PAD_ + k0);
                uint32_t bf[2] = { f2tf(bb.x), f2tf(bb.y) };
                #pragma unroll
                for (int i = 0; i < 4; ++i) mma_tf32(acc[i][j], af[i], bf);
            }
        }
        __syncthreads();
    }

    const int row0 = m0 + wm + qr;
    const int col0 = n0 + wn + tc * 2;

    #pragma unroll
    for (int i = 0; i < 4; ++i) {
        #pragma unroll
        for (int half = 0; half < 2; ++half) {
            const int r = row0 + i * 16 + half * 8;
            float*       crow = C + (size_t)r * ldc;
            const float* rrow = resid ? resid + (size_t)r * ldc : nullptr;
            const float* yrow = yv    ? yv    + (size_t)r * ldc : nullptr;
            #pragma unroll
            for (int j = 0; j < 4; ++j) {
                const int cc = col0 + j * 8;
                float v0 = acc[i][j][half * 2 + 0];
                float v1 = acc[i][j][half * 2 + 1];
                if (mode == 0) {
                    *(float2*)(crow + cc) = make_float2(v0, v1);
                } else if (mode == 1) {
                    float2 bi = *(const float2*)(bias + cc);
                    float2 rv = *(const float2*)(rrow + cc);
                    float2 yw = *(const float2*)(yrow + cc);
                    float g0 = 1.f / (1.f + __expf(-(v0 + bi.x)));
                    float g1 = 1.f / (1.f + __expf(-(v1 + bi.y)));
                    *(float2*)(crow + cc) = make_float2(
                        g0 * rv.x + (1.f - g0) * yw.x,
                        g1 * rv.y + (1.f - g1) * yw.y);
                } else {
                    float2 bi = *(const float2*)(bias + cc);
                    float2 rv = *(const float2*)(rrow + cc);
                    *(float2*)(crow + cc) = make_float2(v0 + bi.x + rv.x,
                                                        v1 + bi.y + rv.y);
                }
            }
        }
    }
}

// QKV with fused LN on A.
__global__ __launch_bounds__(256, 2)
void gemm_qkv(const float* __restrict__ A,
              const float2* __restrict__ lnst,
              const float* __restrict__ lng, const float* __restrict__ lnb,
              const float* __restrict__ Wq, const float* __restrict__ Wk,
              const float* __restrict__ Wv,
              float* __restrict__ q, float* __restrict__ k, float* __restrict__ v)
{
    const int bx  = blockIdx.x;
    const int sel = bx % 3;
    const int m0  = (bx / 3) * 128;
    const float* Bw = (sel == 0) ? Wq : (sel == 1) ? Wk : Wv;
    float*       C  = (sel == 0) ? q  : (sel == 1) ? k  : v;
    gemm_body<true>(A, 512, A, 512, Bw, nullptr, nullptr, nullptr, C, 128,
                    512, 512, 0, m0, 0, lnst, lng, lnb);
}

template <bool LN>
__global__ __launch_bounds__(256, 2)
void gemm_gen(const float* __restrict__ A0, int lda0,
              const float* __restrict__ A1, int lda1,
              const float* __restrict__ Bw,
              const float* __restrict__ bias,
              const float* __restrict__ resid,
              const float* __restrict__ yv,
              float* __restrict__ C, int K1, int Kw, int mode,
              const float2* __restrict__ lnst,
              const float* __restrict__ lng, const float* __restrict__ lnb)
{
    const int bx = blockIdx.x;
    const int m0 = (bx >> 2) * 128;
    const int n0 = (bx & 3) * 128;
    gemm_body<LN>(A0, lda0, A1, lda1, Bw, bias, resid, yv, C, 512,
                  K1, Kw, mode, m0, n0, lnst, lng, lnb);
}

// ============================ prep kernels ==================================
__global__ void build_beff(const float* __restrict__ gW,
                           const float* __restrict__ V,
                           float* __restrict__ Beff)
{
    const int n = blockIdx.x;
    const int tid = threadIdx.x;
    ((float4*)(Beff + (size_t)n * 640))[tid] =
        ((const float4*)(gW + (size_t)n * 1024))[tid];
    const int h = tid >> 4, r = tid & 15;
    const float* w2 = gW + (size_t)n * 1024 + 512 + h * 64;
    const float* vr = V + (size_t)(h * 16 + r) * 64;
    float s = 0.f;
    #pragma unroll
    for (int d = 0; d < 64; ++d) s = fmaf(w2[d], vr[d], s);
    Beff[(size_t)n * 640 + 512 + tid] = s;
}

__global__ void build_rope(float* __restrict__ rc, float* __restrict__ rs)
{
    const int idx = blockIdx.x * 256 + threadIdx.x;
    const int pos = idx >> 5;
    const int ih  = idx & 31;
    const float theta = expf((float)ih * -0.28782313662425572f);
    float sn, cs;
    sincosf((float)pos * theta, &sn, &cs);
    rc[idx] = cs;  rs[idx] = sn;
}

// ===================== LN stats (mean, rstd per token) ======================
__global__ void ln_stats(const float* __restrict__ x, float2* __restrict__ st)
{
    const int tok  = blockIdx.x * 8 + (threadIdx.x >> 5);
    const int lane = threadIdx.x & 31;
    const float4* xr = (const float4*)(x + (size_t)tok * C_);
    float s = 0.f, q = 0.f;
    #pragma unroll
    for (int p = 0; p < 4; ++p) {
        float4 v = xr[lane + p * 32];
        s += v.x + v.y + v.z + v.w;
        q += v.x * v.x + v.y * v.y + v.z * v.z + v.w * v.w;
    }
    #pragma unroll
    for (int o = 16; o; o >>= 1) {
        s += __shfl_xor_sync(0xffffffffu, s, o);
        q += __shfl_xor_sync(0xffffffffu, q, o);
    }
    if (lane == 0) {
        const float mean = s * (1.f / 512.f);
        const float var  = q * (1.f / 512.f) - mean * mean;
        st[tok] = make_float2(mean, rsqrtf(var + 1e-12f));
    }
}

// ========== mma flash attention, TC expansion + fused O@V, QT q-tiles =======
// Block handles QT consecutive 64-row q-tiles (shared K expansion).
template <int KV_TILES, int QT, bool TIME>
__global__ __launch_bounds__(128)
void attn_tc(const float* __restrict__ qlo, const float* __restrict__ klo,
             const float* __restrict__ vlow, const float* __restrict__ U,
             const float* __restrict__ Vw,
             const float* __restrict__ rc, const float* __restrict__ rs,
             float* __restrict__ olow, float* __restrict__ y)
{
    extern __shared__ float sm[];
    float* lot = sm + AT_LOT;
    float* ks  = sm + AT_KS;
    float* vs  = sm + AT_VS;

    const int tid  = threadIdx.x;
    const int lane = tid & 31;
    const int w    = tid >> 5;
    const int head = blockIdx.y;

    int base, step;
    if (TIME) {
        const int b = blockIdx.x >> 8;
        const int l = blockIdx.x & 255;
        base = b * (T_ * L_) + l;  step = L_;
    } else {
        base = blockIdx.x * L_;    step = 1;
    }
    const int q0 = blockIdx.z * (64 * QT);

    const int qr = lane >> 2;
    const int c  = lane & 3;

    uint32_t ub[8][2][2];
    #pragma unroll
    for (int j = 0; j < 8; ++j) {
        const float* up = U + ((size_t)head * 64 + j * 8 + qr) * 16 + 2 * c;
        float2 u0 = __ldg((const float2*)up);
        float2 u1 = __ldg((const float2*)(up + 8));
        ub[j][0][0] = f2tf(u0.x); ub[j][0][1] = f2tf(u0.y);
        ub[j][1][0] = f2tf(u1.x); ub[j][1][1] = f2tf(u1.y);
    }

    // ---- expand Q for each q-subtile -> qa[qt] ----
    uint32_t qa[QT][8][4];
    #pragma unroll
    for (int qt = 0; qt < QT; ++qt) {
        #pragma unroll
        for (int p = 0; p < 2; ++p) {
            const int idx = tid + p * 128;
            const int i = idx >> 2, r4 = (idx & 3) * 4;
            const int tok = base + (q0 + qt * 64 + i) * step;
            *(float4*)&lot[i * LOP_ + r4] =
                *(const float4*)(qlo + (size_t)tok * RK_ + head * 16 + r4);
        }
        __syncthreads();
        {
            const float* a_s = lot + (w * 16 + qr) * LOP_ + 2 * c;
            float2 a00 = *(const float2*)(a_s);
            float2 a01 = *(const float2*)(a_s + 8 * LOP_);
            float2 a10 = *(const float2*)(a_s + 8);
            float2 a11 = *(const float2*)(a_s + 8 * LOP_ + 8);
            uint32_t af0[4] = { f2tf(a00.x), f2tf(a01.x), f2tf(a00.y), f2tf(a01.y) };
            uint32_t af1[4] = { f2tf(a10.x), f2tf(a11.x), f2tf(a10.y), f2tf(a11.y) };
            const int pos0 = q0 + qt * 64 + w * 16 + qr;
            #pragma unroll
            for (int j = 0; j < 8; ++j) {
                float e[4] = {0.f, 0.f, 0.f, 0.f};
                mma_tf32(e, af0, ub[j][0]);
                mma_tf32(e, af1, ub[j][1]);
                const int ih = 4 * j + c;
                const float cs0 = __ldg(rc + pos0 * 32 + ih);
                const float sn0 = __ldg(rs + pos0 * 32 + ih);
                const float cs1 = __ldg(rc + (pos0 + 8) * 32 + ih);
                const float sn1 = __ldg(rs + (pos0 + 8) * 32 + ih);
                qa[qt][j][0] = f2tf((e[0] * cs0 - e[1] * sn0) * 0.125f);
                qa[qt][j][1] = f2tf((e[2] * cs1 - e[3] * sn1) * 0.125f);
                qa[qt][j][2] = f2tf((e[0] * sn0 + e[1] * cs0) * 0.125f);
                qa[qt][j][3] = f2tf((e[2] * sn1 + e[3] * cs1) * 0.125f);
            }
        }
        __syncthreads();
    }

    float m0v[QT], m1v[QT], l0v[QT], l1v[QT];
    float accO[QT][2][4];
    #pragma unroll
    for (int qt = 0; qt < QT; ++qt) {
        m0v[qt] = -1e30f; m1v[qt] = -1e30f; l0v[qt] = 0.f; l1v[qt] = 0.f;
        #pragma unroll
        for (int nf = 0; nf < 2; ++nf)
            #pragma unroll
            for (int r = 0; r < 4; ++r) accO[qt][nf][r] = 0.f;
    }

    for (int kt = 0; kt < KV_TILES; ++kt) {
        // ---- load klo tile + V tile (ONCE per block) ----
        #pragma unroll
        for (int p = 0; p < 2; ++p) {
            const int idx = tid + p * 128;
            const int i = idx >> 2, r4 = (idx & 3) * 4;
            const int tok = base + (kt * 64 + i) * step;
            *(float4*)&lot[i * LOP_ + r4] =
                *(const float4*)(klo + (size_t)tok * RK_ + head * 16 + r4);
        }
        #pragma unroll
        for (int p = 0; p < 2; ++p) {
            const int f = tid + p * 128;
            const int j = f >> 2;
            const int rq = (f & 3) * 4;
            const int tok = base + (kt * 64 + j) * step;
            *(float4*)&vs[j * VP_ + rq] =
                *(const float4*)(vlow + (size_t)tok * RK_ + head * 16 + rq);
        }
        __syncthreads();

        // ---- expand K (ONCE per block) ----
        {
            const float* a_s = lot + (w * 16 + qr) * LOP_ + 2 * c;
            float2 a00 = *(const float2*)(a_s);
            float2 a01 = *(const float2*)(a_s + 8 * LOP_);
            float2 a10 = *(const float2*)(a_s + 8);
            float2 a11 = *(const float2*)(a_s + 8 * LOP_ + 8);
            uint32_t af0[4] = { f2tf(a00.x), f2tf(a01.x), f2tf(a00.y), f2tf(a01.y) };
            uint32_t af1[4] = { f2tf(a10.x), f2tf(a11.x), f2tf(a10.y), f2tf(a11.y) };
            const int krow = w * 16 + qr;
            const int pos0 = kt * 64 + krow;
            #pragma unroll
            for (int j = 0; j < 8; ++j) {
                float e[4] = {0.f, 0.f, 0.f, 0.f};
                mma_tf32(e, af0, ub[j][0]);
                mma_tf32(e, af1, ub[j][1]);
                const int ih = 4 * j + c;
                const float cs0 = __ldg(rc + pos0 * 32 + ih);
                const float sn0 = __ldg(rs + pos0 * 32 + ih);
                const float cs1 = __ldg(rc + (pos0 + 8) * 32 + ih);
                const float sn1 = __ldg(rs + (pos0 + 8) * 32 + ih);
                *(float2*)&ks[krow * QKP_ + j * 8 + 2 * c] =
                    make_float2(e[0] * cs0 - e[1] * sn0,
                                e[0] * sn0 + e[1] * cs0);
                *(float2*)&ks[(krow + 8) * QKP_ + j * 8 + 2 * c] =
                    make_float2(e[2] * cs1 - e[3] * sn1,
                                e[2] * sn1 + e[3] * cs1);
            }
        }
        __syncthreads();

        // ---- per q-subtile: scores, softmax, PV ----
        #pragma unroll
        for (int qt = 0; qt < QT; ++qt) {
            float s[8][4];
            #pragma unroll
            for (int j = 0; j < 8; ++j)
                #pragma unroll
                for (int r = 0; r < 4; ++r) s[j][r] = 0.f;

            const float* b_s = ks + qr * QKP_ + 2 * c;
            #pragma unroll
            for (int ks8 = 0; ks8 < 8; ++ks8) {
                const int k0 = ks8 * 8;
                #pragma unroll
                for (int j = 0; j < 8; ++j) {
                    float2 bb = *(const float2*)(b_s + j * 8 * QKP_ + k0);
                    uint32_t bf[2] = { f2tf(bb.x), f2tf(bb.y) };
                    mma_tf32(s[j], qa[qt][ks8], bf);
                }
            }

            float tm0 = -1e30f, tm1 = -1e30f;
            #pragma unroll
            for (int j = 0; j < 8; ++j) {
                tm0 = fmaxf(tm0, fmaxf(s[j][0], s[j][1]));
                tm1 = fmaxf(tm1, fmaxf(s[j][2], s[j][3]));
            }
            tm0 = fmaxf(tm0, __shfl_xor_sync(0xffffffffu, tm0, 1));
            tm0 = fmaxf(tm0, __shfl_xor_sync(0xffffffffu, tm0, 2));
            tm1 = fmaxf(tm1, __shfl_xor_sync(0xffffffffu, tm1, 1));
            tm1 = fmaxf(tm1, __shfl_xor_sync(0xffffffffu, tm1, 2));

            const float mn0 = fmaxf(m0v[qt], tm0);
            const float mn1 = fmaxf(m1v[qt], tm1);
            const float al0 = __expf(m0v[qt] - mn0);
            const float al1 = __expf(m1v[qt] - mn1);
            m0v[qt] = mn0; m1v[qt] = mn1;

            float rs0 = 0.f, rs1 = 0.f;
            #pragma unroll
            for (int j = 0; j < 8; ++j) {
                s[j][0] = __expf(s[j][0] - mn0);
                s[j][1] = __expf(s[j][1] - mn0);
                s[j][2] = __expf(s[j][2] - mn1);
                s[j][3] = __expf(s[j][3] - mn1);
                rs0 += s[j][0] + s[j][1];
                rs1 += s[j][2] + s[j][3];
            }
            rs0 += __shfl_xor_sync(0xffffffffu, rs0, 1);
            rs0 += __shfl_xor_sync(0xffffffffu, rs0, 2);
            rs1 += __shfl_xor_sync(0xffffffffu, rs1, 1);
            rs1 += __shfl_xor_sync(0xffffffffu, rs1, 2);
            l0v[qt] = l0v[qt] * al0 + rs0;
            l1v[qt] = l1v[qt] * al1 + rs1;

            #pragma unroll
            for (int nf = 0; nf < 2; ++nf) {
                accO[qt][nf][0] *= al0; accO[qt][nf][1] *= al0;
                accO[qt][nf][2] *= al1; accO[qt][nf][3] *= al1;
            }

            #pragma unroll
            for (int j = 0; j < 8; ++j) {
                uint32_t pa[4];
                pa[0] = f2tf(s[j][0]);
                pa[1] = f2tf(s[j][2]);
                pa[2] = f2tf(s[j][1]);
                pa[3] = f2tf(s[j][3]);
                const float* vp = vs + (j * 8 + 2 * c) * VP_;
                #pragma unroll
                for (int nf = 0; nf < 2; ++nf) {
                    const int col = nf * 8 + qr;
                    uint32_t bf[2] = { f2tf(vp[col]), f2tf(vp[VP_ + col]) };
                    mma_tf32(accO[qt][nf], pa, bf);
                }
            }
        }
        __syncthreads();
    }

    // ---- epilogue per q-subtile: olow + fused y = O @ V[h] ----
    const float* Vh = Vw + (size_t)head * 1024;
    #pragma unroll
    for (int qt = 0; qt < QT; ++qt) {
        const float inv0 = 1.f / l0v[qt];
        const float inv1 = 1.f / l1v[qt];
        const int r0 = q0 + qt * 64 + w * 16 + qr;
        const int r1 = r0 + 8;
        const size_t tok0 = (size_t)(base + r0 * step);
        const size_t tok1 = (size_t)(base + r1 * step);

        #pragma unroll
        for (int nf = 0; nf < 2; ++nf) {
            const int col = nf * 8 + c * 2;
            *(float2*)(olow + tok0 * RK_ + head * 16 + col) =
                make_float2(accO[qt][nf][0] * inv0, accO[qt][nf][1] * inv0);
            *(float2*)(olow + tok1 * RK_ + head * 16 + col) =
                make_float2(accO[qt][nf][2] * inv1, accO[qt][nf][3] * inv1);
        }

        uint32_t oa[2][4];
        #pragma unroll
        for (int s2 = 0; s2 < 2; ++s2) {
            oa[s2][0] = f2tf(accO[qt][s2][0] * inv0);
            oa[s2][1] = f2tf(accO[qt][s2][2] * inv1);
            oa[s2][2] = f2tf(accO[qt][s2][1] * inv0);
            oa[s2][3] = f2tf(accO[qt][s2][3] * inv1);
        }
        #pragma unroll
        for (int j = 0; j < 8; ++j) {
            float ya[4] = {0.f, 0.f, 0.f, 0.f};
            #pragma unroll
            for (int s2 = 0; s2 < 2; ++s2) {
                const int rr = s2 * 8 + 2 * c;
                uint32_t bf[2] = { f2tf(__ldg(Vh + rr * 64 + j * 8 + qr)),
                                   f2tf(__ldg(Vh + (rr + 1) * 64 + j * 8 + qr)) };
                mma_tf32(ya, oa[s2], bf);
            }
            const int dcol = head * 64 + j * 8 + 2 * c;
            *(float2*)(y + tok0 * C_ + dcol) = make_float2(ya[0], ya[1]);
            *(float2*)(y + tok1 * C_ + dcol) = make_float2(ya[2], ya[3]);
        }
    }
}

// ============================ launch ========================================
extern "C" void kernel_launch(void* const* d_in, const int* in_sizes, int n_in,
                              void* d_out, int out_size)
{
    const float* x    = (const float*)d_in[0];
    const float* tWq  = (const float*)d_in[3];
    const float* tWk  = (const float*)d_in[4];
    const float* tWv  = (const float*)d_in[5];
    const float* tU   = (const float*)d_in[6];
    const float* tV   = (const float*)d_in[7];
    const float* aWq  = (const float*)d_in[8];
    const float* aWk  = (const float*)d_in[9];
    const float* aWv  = (const float*)d_in[10];
    const float* aU   = (const float*)d_in[11];
    const float* aV   = (const float*)d_in[12];
    const float* ln1g = (const float*)d_in[13];
    const float* ln1b = (const float*)d_in[14];
    const float* ln2g = (const float*)d_in[15];
    const float* ln2b = (const float*)d_in[16];
    const float* ln3g = (const float*)d_in[17];
    const float* ln3b = (const float*)d_in[18];
    const float* projW= (const float*)d_in[19];
    const float* projb= (const float*)d_in[20];
    const float* gtW  = (const float*)d_in[21];
    const float* gtb  = (const float*)d_in[22];
    const float* gaW  = (const float*)d_in[23];
    const float* gab  = (const float*)d_in[24];
    float* out = (float*)d_out;

    float *yb, *x1, *x2, *qlo, *klo, *vlo, *olo;
    float *befft, *beffa, *ropec, *ropes;
    float2* stp;
    cudaGetSymbolAddress((void**)&yb,  g_y);
    cudaGetSymbolAddress((void**)&x1,  g_x1);
    cudaGetSymbolAddress((void**)&x2,  g_x2);
    cudaGetSymbolAddress((void**)&qlo, g_qlo);
    cudaGetSymbolAddress((void**)&klo, g_klo);
    cudaGetSymbolAddress((void**)&vlo, g_vlo);
    cudaGetSymbolAddress((void**)&olo, g_olo);
    cudaGetSymbolAddress((void**)&befft, g_befft);
    cudaGetSymbolAddress((void**)&beffa, g_beffa);
    cudaGetSymbolAddress((void**)&ropec, g_ropec);
    cudaGetSymbolAddress((void**)&ropes, g_ropes);
    cudaGetSymbolAddress((void**)&stp,  g_st);

    static bool attr_set = false;
    if (!attr_set) {
        cudaFuncSetAttribute(gemm_qkv, cudaFuncAttributeMaxDynamicSharedMemorySize, GEMM_SMEM);
        cudaFuncSetAttribute(gemm_gen<false>, cudaFuncAttributeMaxDynamicSharedMemorySize, GEMM_SMEM);
        cudaFuncSetAttribute(gemm_gen<true>,  cudaFuncAttributeMaxDynamicSharedMemorySize, GEMM_SMEM);
        cudaFuncSetAttribute(attn_tc<1, 1, true>,  cudaFuncAttributeMaxDynamicSharedMemorySize, ATTN_SMEM);
        cudaFuncSetAttribute(attn_tc<4, 2, false>, cudaFuncAttributeMaxDynamicSharedMemorySize, ATTN_SMEM);
        attr_set = true;
    }

    // -------- prep --------
    build_rope<<<32, 256>>>(ropec, ropes);
    build_beff<<<512, 128>>>(gtW, tV, befft);
    build_beff<<<512, 128>>>(gaW, aV, beffa);

    // ---------------- stage A: time attention ----------------
    ln_stats<<<N_ / 8, 256>>>(x, stp);
    gemm_qkv<<<3 * (N_ / 128), 256, GEMM_SMEM>>>(x, stp, ln1g, ln1b,
                                                 tWq, tWk, tWv, qlo, klo, vlo);
    attn_tc<1, 1, true><<<dim3(B_ * L_, 8, 1), 128, ATTN_SMEM>>>(
        qlo, klo, vlo, tU, tV, ropec, ropes, olo, yb);
    gemm_gen<false><<<4 * (N_ / 128), 256, GEMM_SMEM>>>(
        x, 512, olo, 128, befft, gtb, x, yb, x1, 512, 640, 1,
        nullptr, nullptr, nullptr);

    // ---------------- stage B: residue attention ----------------
    ln_stats<<<N_ / 8, 256>>>(x1, stp);
    gemm_qkv<<<3 * (N_ / 128), 256, GEMM_SMEM>>>(x1, stp, ln2g, ln2b,
                                                 aWq, aWk, aWv, qlo, klo, vlo);
    attn_tc<4, 2, false><<<dim3(B_ * T_, 8, 2), 128, ATTN_SMEM>>>(
        qlo, klo, vlo, aU, aV, ropec, ropes, olo, yb);
    gemm_gen<false><<<4 * (N_ / 128), 256, GEMM_SMEM>>>(
        x1, 512, olo, 128, beffa, gab, x1, yb, x2, 512, 640, 1,
        nullptr, nullptr, nullptr);

    // ---------------- stage C: output projection ----------------
    ln_stats<<<N_ / 8, 256>>>(x2, stp);
    gemm_gen<true><<<4 * (N_ / 128), 256, GEMM_SMEM>>>(
        x2, 512, x2, 512, projW, projb, x2, nullptr, out, 512, 512, 2,
        stp, ln3g, ln3b);
}